// round 1
// baseline (speedup 1.0000x reference)
#include <cuda_runtime.h>
#include <cstdint>
#include <cstddef>
#include <math.h>

// Problem constants (fixed dataset)
#define B_   2
#define E_   160000
#define N_   10000
#define FIN_ 24
#define D_   128
#define P2E_ (2 * E_)

// ---------------- scratch (static __device__, no allocations) ----------------
__device__ float g_emb[(size_t)B_ * E_ * D_];     // edge embeddings [B][E][128]
__device__ float g_edot[2][(size_t)B_ * E_];      // per-layer e_pair . watt[128:256]
__device__ float g_nodeA[(size_t)B_ * N_ * D_];   // node emb after layer 1
__device__ float g_nodeB[(size_t)B_ * N_ * D_];   // node emb after layer 2
__device__ int   g_cnt[N_];
__device__ int   g_cur[N_];
__device__ int   g_off[N_ + 1];
__device__ int   g_adj[P2E_];

// ---------------- helpers ----------------
__device__ __forceinline__ float gelu_f(float x) {
    return 0.5f * x * (1.0f + erff(x * 0.70710678118654752f));
}
__device__ __forceinline__ float wsum(float v) {
#pragma unroll
    for (int o = 16; o; o >>= 1) v += __shfl_xor_sync(0xffffffffu, v, o);
    return v;
}
__device__ __forceinline__ float wmax(float v) {
#pragma unroll
    for (int o = 16; o; o >>= 1) v = fmaxf(v, __shfl_xor_sync(0xffffffffu, v, o));
    return v;
}

// ---------------- CSR build ----------------
__global__ void zero_cnt_kernel() {
    int i = blockIdx.x * blockDim.x + threadIdx.x;
    if (i < N_) g_cnt[i] = 0;
}

__global__ void count_kernel(const int* __restrict__ src, const int* __restrict__ dst) {
    int idx = blockIdx.x * blockDim.x + threadIdx.x;
    if (idx >= P2E_) return;
    int node = (idx < E_) ? src[idx] : dst[idx - E_];
    atomicAdd(&g_cnt[node], 1);
}

__global__ void scan_kernel() {
    __shared__ int ss[1024];
    int t = threadIdx.x;
    int base = t * 10;                  // 1024*10 >= N_
    int s = 0;
#pragma unroll
    for (int i = 0; i < 10; i++) {
        int idx = base + i;
        if (idx < N_) s += g_cnt[idx];
    }
    ss[t] = s;
    __syncthreads();
    for (int off = 1; off < 1024; off <<= 1) {
        int v = (t >= off) ? ss[t - off] : 0;
        __syncthreads();
        ss[t] += v;
        __syncthreads();
    }
    int run = (t > 0) ? ss[t - 1] : 0;
#pragma unroll
    for (int i = 0; i < 10; i++) {
        int idx = base + i;
        if (idx < N_) {
            g_off[idx] = run;
            run += g_cnt[idx];
            g_cur[idx] = 0;
        }
    }
    if (t == 1023) g_off[N_] = ss[1023];
}

__global__ void fill_kernel(const int* __restrict__ src, const int* __restrict__ dst) {
    int idx = blockIdx.x * blockDim.x + threadIdx.x;
    if (idx >= P2E_) return;
    int node = (idx < E_) ? src[idx] : dst[idx - E_];
    int e    = (idx < E_) ? idx : idx - E_;
    int pos = g_off[node] + atomicAdd(&g_cur[node], 1);
    g_adj[pos] = e;
}

// ---------------- fused edge encoder ----------------
// grid (E/32, B), 256 threads; each warp owns 4 rows.
// smem floats layout:
//   W1s 0..3071 | W2s 3072..19455 | xs 19456..20223 | ht 20224..24831 (128x36)
//   vb1 24832 vg1 24960 vbe1 25088 vb2 25216 vg2 25344 vbe2 25472 we1 25600 we2 25728
#define ENC_SMEM_FLOATS 25856
__global__ void __launch_bounds__(256, 2) encoder_kernel(
    const float* __restrict__ xin,
    const float* __restrict__ w1, const float* __restrict__ b1,
    const float* __restrict__ g1, const float* __restrict__ be1,
    const float* __restrict__ w2, const float* __restrict__ b2,
    const float* __restrict__ g2, const float* __restrict__ be2,
    const float* __restrict__ watt1, const float* __restrict__ watt2)
{
    extern __shared__ float sm[];
    float* W1s  = sm;
    float* W2s  = sm + 3072;
    float* xs   = sm + 19456;
    float* ht   = sm + 20224;   // [128][36] transposed h
    float* vb1  = sm + 24832;
    float* vg1  = sm + 24960;
    float* vbe1 = sm + 25088;
    float* vb2  = sm + 25216;
    float* vg2  = sm + 25344;
    float* vbe2 = sm + 25472;
    float* we1  = sm + 25600;
    float* we2  = sm + 25728;

    int tid = threadIdx.x;
    int b = blockIdx.y;
    int e0 = blockIdx.x * 32;

    for (int i = tid; i < FIN_ * D_; i += 256) W1s[i] = w1[i];
    for (int i = tid; i < D_ * D_; i += 256)   W2s[i] = w2[i];
    if (tid < 128) {
        vb1[tid] = b1[tid];  vg1[tid] = g1[tid];  vbe1[tid] = be1[tid];
        vb2[tid] = b2[tid];  vg2[tid] = g2[tid];  vbe2[tid] = be2[tid];
        we1[tid] = watt1[128 + tid];
        we2[tid] = watt2[128 + tid];
    }
    {
        size_t base = ((size_t)b * E_ + e0) * FIN_;
        for (int i = tid; i < 32 * FIN_; i += 256) xs[i] = xin[base + i];
    }
    __syncthreads();

    int warp = tid >> 5, lane = tid & 31;
    int r0 = warp * 4;
    int c0 = lane * 4;

    // GEMM1: h[32][128] = x[32][24] @ W1
    float acc[4][4];
#pragma unroll
    for (int r = 0; r < 4; r++)
#pragma unroll
        for (int j = 0; j < 4; j++) acc[r][j] = 0.f;

#pragma unroll
    for (int k = 0; k < FIN_; k++) {
        float4 wv = *(float4*)&W1s[k * D_ + c0];
#pragma unroll
        for (int r = 0; r < 4; r++) {
            float a = xs[(r0 + r) * FIN_ + k];
            acc[r][0] = fmaf(a, wv.x, acc[r][0]);
            acc[r][1] = fmaf(a, wv.y, acc[r][1]);
            acc[r][2] = fmaf(a, wv.z, acc[r][2]);
            acc[r][3] = fmaf(a, wv.w, acc[r][3]);
        }
    }
    // +b1, LN1, gelu -> ht (transposed)
#pragma unroll
    for (int r = 0; r < 4; r++) {
        float v[4];
#pragma unroll
        for (int j = 0; j < 4; j++) v[j] = acc[r][j] + vb1[c0 + j];
        float s = wsum(v[0] + v[1] + v[2] + v[3]);
        float mu = s * (1.f / 128.f);
        float d[4], q = 0.f;
#pragma unroll
        for (int j = 0; j < 4; j++) { d[j] = v[j] - mu; q += d[j] * d[j]; }
        q = wsum(q);
        float rstd = rsqrtf(q * (1.f / 128.f) + 1e-5f);
#pragma unroll
        for (int j = 0; j < 4; j++) {
            float nv = d[j] * rstd * vg1[c0 + j] + vbe1[c0 + j];
            ht[(c0 + j) * 36 + r0 + r] = gelu_f(nv);
        }
    }
    __syncwarp();

    // GEMM2: out[32][128] = gelu(h) @ W2
    float acc2[4][4];
#pragma unroll
    for (int r = 0; r < 4; r++)
#pragma unroll
        for (int j = 0; j < 4; j++) acc2[r][j] = 0.f;

#pragma unroll 8
    for (int k = 0; k < D_; k++) {
        float4 av = *(float4*)&ht[k * 36 + r0];
        float4 wv = *(float4*)&W2s[k * D_ + c0];
        float a[4] = {av.x, av.y, av.z, av.w};
        float w[4] = {wv.x, wv.y, wv.z, wv.w};
#pragma unroll
        for (int r = 0; r < 4; r++)
#pragma unroll
            for (int j = 0; j < 4; j++)
                acc2[r][j] = fmaf(a[r], w[j], acc2[r][j]);
    }
    // +b2, LN2 -> emb ; e_dot epilogue for both layers
#pragma unroll
    for (int r = 0; r < 4; r++) {
        float v[4];
#pragma unroll
        for (int j = 0; j < 4; j++) v[j] = acc2[r][j] + vb2[c0 + j];
        float s = wsum(v[0] + v[1] + v[2] + v[3]);
        float mu = s * (1.f / 128.f);
        float d[4], q = 0.f;
#pragma unroll
        for (int j = 0; j < 4; j++) { d[j] = v[j] - mu; q += d[j] * d[j]; }
        q = wsum(q);
        float rstd = rsqrtf(q * (1.f / 128.f) + 1e-5f);
        float y[4];
#pragma unroll
        for (int j = 0; j < 4; j++)
            y[j] = d[j] * rstd * vg2[c0 + j] + vbe2[c0 + j];

        size_t row = (size_t)b * E_ + e0 + r0 + r;
        *(float4*)&g_emb[row * D_ + c0] = make_float4(y[0], y[1], y[2], y[3]);

        float p1 = 0.f, p2 = 0.f;
#pragma unroll
        for (int j = 0; j < 4; j++) {
            p1 = fmaf(y[j], we1[c0 + j], p1);
            p2 = fmaf(y[j], we2[c0 + j], p2);
        }
        p1 = wsum(p1);
        p2 = wsum(p2);
        if (lane == 0) {
            g_edot[0][row] = p1;
            g_edot[1][row] = p2;
        }
    }
}

// ---------------- message passing (one warp per (batch, node)) ----------------
__global__ void mp_kernel(const float* __restrict__ watt,
                          const float* __restrict__ batt_p, int layer)
{
    int w = (blockIdx.x * blockDim.x + threadIdx.x) >> 5;
    int lane = threadIdx.x & 31;
    if (w >= B_ * N_) return;
    int b = w / N_, n = w % N_;

    const float* node_in = g_nodeA;                 // only read when layer==1
    float* node_out = (layer == 0) ? g_nodeA : g_nodeB;

    float batt = batt_p[0];
    float hd = 0.f;
    float4 cur = make_float4(0.f, 0.f, 0.f, 0.f);
    size_t nrow = ((size_t)b * N_ + n) * D_ + lane * 4;
    if (layer > 0) {
        cur = *(const float4*)&node_in[nrow];
        float4 wh = *(const float4*)&watt[lane * 4];
        float p = cur.x * wh.x + cur.y * wh.y + cur.z * wh.z + cur.w * wh.w;
        hd = wsum(p);
    }

    int start = g_off[n], end = g_off[n + 1];
    int deg = end - start;
    if (deg == 0) {                       // where(deg>0, new, node_b)
        *(float4*)&node_out[nrow] = cur;  // layer0: zeros; layer1: pass-through
        return;
    }

    const float* edot = &g_edot[layer][(size_t)b * E_];

    float m = -1e30f;
    for (int i = start + lane; i < end; i += 32) {
        float s = hd + edot[g_adj[i]] + batt;
        s = (s > 0.f) ? s : 0.2f * s;
        m = fmaxf(m, s);
    }
    m = wmax(m);

    float den = 0.f;
    for (int i = start + lane; i < end; i += 32) {
        float s = hd + edot[g_adj[i]] + batt;
        s = (s > 0.f) ? s : 0.2f * s;
        den += expf(s - m);
    }
    den = wsum(den);

    float4 acc = make_float4(0.f, 0.f, 0.f, 0.f);
    for (int i = start; i < end; i++) {
        int e = g_adj[i];
        float s = hd + edot[e] + batt;
        s = (s > 0.f) ? s : 0.2f * s;
        float p = expf(s - m);
        const float4 v = *(const float4*)&g_emb[((size_t)b * E_ + e) * D_ + lane * 4];
        acc.x = fmaf(p, v.x, acc.x);
        acc.y = fmaf(p, v.y, acc.y);
        acc.z = fmaf(p, v.z, acc.z);
        acc.w = fmaf(p, v.w, acc.w);
    }
    float inv = 1.f / den;
    float4 outv;
    outv.x = gelu_f(acc.x * inv);
    outv.y = gelu_f(acc.y * inv);
    outv.z = gelu_f(acc.z * inv);
    outv.w = gelu_f(acc.w * inv);
    *(float4*)&node_out[nrow] = outv;
}

// ---------------- fused decoder ----------------
// grid (E/64, B), 256 threads; 64 rows per block.
// smem floats: z1s[64*256]=16384 | wbuf 8192 | cats 64*32=2048 |
//              b1s 256 | b2s 128 | w3s 128 | sn 64 | dn 64  -> 27264 floats
#define DEC_SMEM_FLOATS 27264
__global__ void __launch_bounds__(256, 2) decoder_kernel(
    const float* __restrict__ w1, const float* __restrict__ b1,
    const float* __restrict__ w2, const float* __restrict__ b2,
    const float* __restrict__ w3, const float* __restrict__ b3,
    const int* __restrict__ src, const int* __restrict__ dst,
    float* __restrict__ out)
{
    extern __shared__ float sm[];
    float* z1s  = sm;            // [64][256] activated z1
    float* wbuf = sm + 16384;    // weight k-chunk
    float* cats = sm + 24576;    // [64][32] cat k-chunk
    float* b1s  = sm + 26624;
    float* b2s  = sm + 26880;
    float* w3s  = sm + 27008;
    int* sn = (int*)(sm + 27136);
    int* dn = (int*)(sm + 27200);

    int tid = threadIdx.x;
    int tc = tid & 31;          // col group
    int tr = tid >> 5;          // row group (0..7)
    int b = blockIdx.y;
    int e0 = blockIdx.x * 64;

    if (tid < 64) { sn[tid] = src[e0 + tid]; dn[tid] = dst[e0 + tid]; }
    b1s[tid] = b1[tid];
    if (tid < 128) { b2s[tid] = b2[tid]; w3s[tid] = w3[tid]; }

    const float* nodeb = g_nodeB + (size_t)b * N_ * D_;
    const float* embb  = g_emb   + (size_t)b * E_ * D_;

    float acc[8][8];
#pragma unroll
    for (int i = 0; i < 8; i++)
#pragma unroll
        for (int j = 0; j < 8; j++) acc[i][j] = 0.f;

    // GEMM1: z1[64][256] = cat[64][384] @ W1
    for (int kc = 0; kc < 384; kc += 32) {
        __syncthreads();
        for (int i = tid; i < 32 * 256; i += 256)
            wbuf[i] = w1[(kc + (i >> 8)) * 256 + (i & 255)];
        for (int i = tid; i < 64 * 32; i += 256) {
            int r = i >> 5, kk = i & 31;
            float v;
            if (kc < 128)      v = nodeb[(size_t)sn[r] * D_ + kc + kk];
            else if (kc < 256) v = nodeb[(size_t)dn[r] * D_ + kc - 128 + kk];
            else               v = embb[(size_t)(e0 + r) * D_ + kc - 256 + kk];
            cats[i] = v;
        }
        __syncthreads();
#pragma unroll 8
        for (int kk = 0; kk < 32; kk++) {
            float4 q0 = *(float4*)&wbuf[kk * 256 + tc * 8];
            float4 q1 = *(float4*)&wbuf[kk * 256 + tc * 8 + 4];
            float bb[8] = {q0.x, q0.y, q0.z, q0.w, q1.x, q1.y, q1.z, q1.w};
            float aa[8];
#pragma unroll
            for (int i = 0; i < 8; i++) aa[i] = cats[(tr * 8 + i) * 32 + kk];
#pragma unroll
            for (int i = 0; i < 8; i++)
#pragma unroll
                for (int j = 0; j < 8; j++)
                    acc[i][j] = fmaf(aa[i], bb[j], acc[i][j]);
        }
    }
    // bias + gelu -> z1s
#pragma unroll
    for (int i = 0; i < 8; i++) {
#pragma unroll
        for (int j = 0; j < 8; j++)
            acc[i][j] = gelu_f(acc[i][j] + b1s[tc * 8 + j]);
        *(float4*)&z1s[(tr * 8 + i) * 256 + tc * 8] =
            make_float4(acc[i][0], acc[i][1], acc[i][2], acc[i][3]);
        *(float4*)&z1s[(tr * 8 + i) * 256 + tc * 8 + 4] =
            make_float4(acc[i][4], acc[i][5], acc[i][6], acc[i][7]);
    }
    __syncthreads();

    // GEMM2: z2[64][128] = z1 @ W2
    float acc2[8][4];
#pragma unroll
    for (int i = 0; i < 8; i++)
#pragma unroll
        for (int j = 0; j < 4; j++) acc2[i][j] = 0.f;

    for (int kc = 0; kc < 256; kc += 64) {
        if (kc) __syncthreads();
        for (int i = tid; i < 64 * 128; i += 256)
            wbuf[i] = w2[(kc + (i >> 7)) * 128 + (i & 127)];
        __syncthreads();
#pragma unroll 8
        for (int kk = 0; kk < 64; kk++) {
            float4 bq = *(float4*)&wbuf[kk * 128 + tc * 4];
#pragma unroll
            for (int i = 0; i < 8; i++) {
                float a = z1s[(tr * 8 + i) * 256 + kc + kk];
                acc2[i][0] = fmaf(a, bq.x, acc2[i][0]);
                acc2[i][1] = fmaf(a, bq.y, acc2[i][1]);
                acc2[i][2] = fmaf(a, bq.z, acc2[i][2]);
                acc2[i][3] = fmaf(a, bq.w, acc2[i][3]);
            }
        }
    }

    // epilogue: gelu(z2) . w3 + b3
    float part[8];
#pragma unroll
    for (int i = 0; i < 8; i++) {
        float s = 0.f;
#pragma unroll
        for (int j = 0; j < 4; j++) {
            float v = gelu_f(acc2[i][j] + b2s[tc * 4 + j]);
            s = fmaf(v, w3s[tc * 4 + j], s);
        }
        part[i] = s;
    }
#pragma unroll
    for (int o = 16; o; o >>= 1)
#pragma unroll
        for (int i = 0; i < 8; i++)
            part[i] += __shfl_xor_sync(0xffffffffu, part[i], o);
    if (tc == 0) {
        float bb3 = b3[0];
#pragma unroll
        for (int i = 0; i < 8; i++)
            out[(size_t)b * E_ + e0 + tr * 8 + i] = part[i] + bb3;
    }
}

// ---------------- launch ----------------
extern "C" void kernel_launch(void* const* d_in, const int* in_sizes, int n_in,
                              void* d_out, int out_size)
{
    const float* edge_features = (const float*)d_in[0];
    const float* enc_w1  = (const float*)d_in[1];
    const float* enc_b1  = (const float*)d_in[2];
    const float* enc_g1  = (const float*)d_in[3];
    const float* enc_be1 = (const float*)d_in[4];
    const float* enc_w2  = (const float*)d_in[5];
    const float* enc_b2  = (const float*)d_in[6];
    const float* enc_g2  = (const float*)d_in[7];
    const float* enc_be2 = (const float*)d_in[8];
    const float* watt1   = (const float*)d_in[9];
    const float* batt1   = (const float*)d_in[10];
    const float* watt2   = (const float*)d_in[11];
    const float* batt2   = (const float*)d_in[12];
    const float* dec_w1  = (const float*)d_in[13];
    const float* dec_b1  = (const float*)d_in[14];
    const float* dec_w2  = (const float*)d_in[15];
    const float* dec_b2  = (const float*)d_in[16];
    const float* dec_w3  = (const float*)d_in[17];
    const float* dec_b3  = (const float*)d_in[18];
    const int*   src     = (const int*)d_in[19];
    const int*   dst     = (const int*)d_in[20];
    float* out = (float*)d_out;

    cudaFuncSetAttribute(encoder_kernel, cudaFuncAttributeMaxDynamicSharedMemorySize,
                         ENC_SMEM_FLOATS * 4);
    cudaFuncSetAttribute(decoder_kernel, cudaFuncAttributeMaxDynamicSharedMemorySize,
                         DEC_SMEM_FLOATS * 4);

    // CSR build (recomputed every call; deterministic work)
    zero_cnt_kernel<<<(N_ + 255) / 256, 256>>>();
    count_kernel<<<(P2E_ + 255) / 256, 256>>>(src, dst);
    scan_kernel<<<1, 1024>>>();
    fill_kernel<<<(P2E_ + 255) / 256, 256>>>(src, dst);

    // fused encoder (+ e_dot epilogues for both attention layers)
    encoder_kernel<<<dim3(E_ / 32, B_), 256, ENC_SMEM_FLOATS * 4>>>(
        edge_features, enc_w1, enc_b1, enc_g1, enc_be1,
        enc_w2, enc_b2, enc_g2, enc_be2, watt1, watt2);

    // message passing: layer 1 (node_in = 0), layer 2
    int mp_blocks = (B_ * N_ + 7) / 8;   // 8 warps/block
    mp_kernel<<<mp_blocks, 256>>>(watt1, batt1, 0);
    mp_kernel<<<mp_blocks, 256>>>(watt2, batt2, 1);

    // fused decoder MLP
    decoder_kernel<<<dim3(E_ / 64, B_), 256, DEC_SMEM_FLOATS * 4>>>(
        dec_w1, dec_b1, dec_w2, dec_b2, dec_w3, dec_b3, src, dst, out);
}

// round 2
// speedup vs baseline: 1.1626x; 1.1626x over previous
#include <cuda_runtime.h>
#include <cstdint>
#include <cstddef>
#include <math.h>

// Problem constants (fixed dataset)
#define B_   2
#define E_   160000
#define N_   10000
#define FIN_ 24
#define D_   128
#define P2E_ (2 * E_)

// ---------------- scratch (static __device__, no allocations) ----------------
__device__ float g_emb[(size_t)B_ * E_ * D_];     // edge embeddings [B][E][128]
__device__ float g_edot[2][(size_t)B_ * E_];      // per-layer e_pair . watt[128:256]
__device__ float g_nodeA[(size_t)B_ * N_ * D_];   // node emb after layer 1
__device__ float g_nodeB[(size_t)B_ * N_ * D_];   // node emb after layer 2
__device__ int   g_cnt[N_];
__device__ int   g_cur[N_];
__device__ int   g_off[N_ + 1];
__device__ int   g_adj[P2E_];
// tf32 hi/lo split decoder weights (fp32 bit patterns holding tf32 values)
__device__ float g_w1hi[384 * 256];
__device__ float g_w1lo[384 * 256];
__device__ float g_w2hi[256 * 128];
__device__ float g_w2lo[256 * 128];

// ---------------- helpers ----------------
__device__ __forceinline__ float gelu_f(float x) {
    return 0.5f * x * (1.0f + erff(x * 0.70710678118654752f));
}
__device__ __forceinline__ float wsum(float v) {
#pragma unroll
    for (int o = 16; o; o >>= 1) v += __shfl_xor_sync(0xffffffffu, v, o);
    return v;
}
__device__ __forceinline__ float wmax(float v) {
#pragma unroll
    for (int o = 16; o; o >>= 1) v = fmaxf(v, __shfl_xor_sync(0xffffffffu, v, o));
    return v;
}
__device__ __forceinline__ uint32_t f2tf32(float x) {
    uint32_t r;
    asm("cvt.rna.tf32.f32 %0, %1;" : "=r"(r) : "f"(x));
    return r;
}
__device__ __forceinline__ void mma_tf32(float* c, uint32_t a0, uint32_t a1,
                                         uint32_t a2, uint32_t a3,
                                         uint32_t b0, uint32_t b1) {
    asm volatile(
        "mma.sync.aligned.m16n8k8.row.col.f32.tf32.tf32.f32 "
        "{%0,%1,%2,%3},{%4,%5,%6,%7},{%8,%9},{%0,%1,%2,%3};"
        : "+f"(c[0]), "+f"(c[1]), "+f"(c[2]), "+f"(c[3])
        : "r"(a0), "r"(a1), "r"(a2), "r"(a3), "r"(b0), "r"(b1));
}

// ---------------- weight split prep ----------------
__global__ void split_weights_kernel(const float* __restrict__ w1,
                                     const float* __restrict__ w2) {
    int i = blockIdx.x * blockDim.x + threadIdx.x;
    if (i < 384 * 256) {
        float x = w1[i];
        uint32_t hb = f2tf32(x);
        float hf = __uint_as_float(hb);
        g_w1hi[i] = hf;
        g_w1lo[i] = __uint_as_float(f2tf32(x - hf));
    }
    int j = i - 384 * 256;
    if (j >= 0 && j < 256 * 128) {
        float x = w2[j];
        uint32_t hb = f2tf32(x);
        float hf = __uint_as_float(hb);
        g_w2hi[j] = hf;
        g_w2lo[j] = __uint_as_float(f2tf32(x - hf));
    }
}

// ---------------- CSR build ----------------
__global__ void zero_cnt_kernel() {
    int i = blockIdx.x * blockDim.x + threadIdx.x;
    if (i < N_) g_cnt[i] = 0;
}

__global__ void count_kernel(const int* __restrict__ src, const int* __restrict__ dst) {
    int idx = blockIdx.x * blockDim.x + threadIdx.x;
    if (idx >= P2E_) return;
    int node = (idx < E_) ? src[idx] : dst[idx - E_];
    atomicAdd(&g_cnt[node], 1);
}

__global__ void scan_kernel() {
    __shared__ int ss[1024];
    int t = threadIdx.x;
    int base = t * 10;                  // 1024*10 >= N_
    int s = 0;
#pragma unroll
    for (int i = 0; i < 10; i++) {
        int idx = base + i;
        if (idx < N_) s += g_cnt[idx];
    }
    ss[t] = s;
    __syncthreads();
    for (int off = 1; off < 1024; off <<= 1) {
        int v = (t >= off) ? ss[t - off] : 0;
        __syncthreads();
        ss[t] += v;
        __syncthreads();
    }
    int run = (t > 0) ? ss[t - 1] : 0;
#pragma unroll
    for (int i = 0; i < 10; i++) {
        int idx = base + i;
        if (idx < N_) {
            g_off[idx] = run;
            run += g_cnt[idx];
            g_cur[idx] = 0;
        }
    }
    if (t == 1023) g_off[N_] = ss[1023];
}

__global__ void fill_kernel(const int* __restrict__ src, const int* __restrict__ dst) {
    int idx = blockIdx.x * blockDim.x + threadIdx.x;
    if (idx >= P2E_) return;
    int node = (idx < E_) ? src[idx] : dst[idx - E_];
    int e    = (idx < E_) ? idx : idx - E_;
    int pos = g_off[node] + atomicAdd(&g_cur[node], 1);
    g_adj[pos] = e;
}

// ---------------- fused edge encoder ----------------
#define ENC_SMEM_FLOATS 25856
__global__ void __launch_bounds__(256, 2) encoder_kernel(
    const float* __restrict__ xin,
    const float* __restrict__ w1, const float* __restrict__ b1,
    const float* __restrict__ g1, const float* __restrict__ be1,
    const float* __restrict__ w2, const float* __restrict__ b2,
    const float* __restrict__ g2, const float* __restrict__ be2,
    const float* __restrict__ watt1, const float* __restrict__ watt2)
{
    extern __shared__ float sm[];
    float* W1s  = sm;
    float* W2s  = sm + 3072;
    float* xs   = sm + 19456;
    float* ht   = sm + 20224;   // [128][36] transposed h
    float* vb1  = sm + 24832;
    float* vg1  = sm + 24960;
    float* vbe1 = sm + 25088;
    float* vb2  = sm + 25216;
    float* vg2  = sm + 25344;
    float* vbe2 = sm + 25472;
    float* we1  = sm + 25600;
    float* we2  = sm + 25728;

    int tid = threadIdx.x;
    int b = blockIdx.y;
    int e0 = blockIdx.x * 32;

    for (int i = tid; i < FIN_ * D_; i += 256) W1s[i] = w1[i];
    for (int i = tid; i < D_ * D_; i += 256)   W2s[i] = w2[i];
    if (tid < 128) {
        vb1[tid] = b1[tid];  vg1[tid] = g1[tid];  vbe1[tid] = be1[tid];
        vb2[tid] = b2[tid];  vg2[tid] = g2[tid];  vbe2[tid] = be2[tid];
        we1[tid] = watt1[128 + tid];
        we2[tid] = watt2[128 + tid];
    }
    {
        size_t base = ((size_t)b * E_ + e0) * FIN_;
        for (int i = tid; i < 32 * FIN_; i += 256) xs[i] = xin[base + i];
    }
    __syncthreads();

    int warp = tid >> 5, lane = tid & 31;
    int r0 = warp * 4;
    int c0 = lane * 4;

    // GEMM1: h[32][128] = x[32][24] @ W1
    float acc[4][4];
#pragma unroll
    for (int r = 0; r < 4; r++)
#pragma unroll
        for (int j = 0; j < 4; j++) acc[r][j] = 0.f;

#pragma unroll
    for (int k = 0; k < FIN_; k++) {
        float4 wv = *(float4*)&W1s[k * D_ + c0];
#pragma unroll
        for (int r = 0; r < 4; r++) {
            float a = xs[(r0 + r) * FIN_ + k];
            acc[r][0] = fmaf(a, wv.x, acc[r][0]);
            acc[r][1] = fmaf(a, wv.y, acc[r][1]);
            acc[r][2] = fmaf(a, wv.z, acc[r][2]);
            acc[r][3] = fmaf(a, wv.w, acc[r][3]);
        }
    }
    // +b1, LN1, gelu -> ht (transposed)
#pragma unroll
    for (int r = 0; r < 4; r++) {
        float v[4];
#pragma unroll
        for (int j = 0; j < 4; j++) v[j] = acc[r][j] + vb1[c0 + j];
        float s = wsum(v[0] + v[1] + v[2] + v[3]);
        float mu = s * (1.f / 128.f);
        float d[4], q = 0.f;
#pragma unroll
        for (int j = 0; j < 4; j++) { d[j] = v[j] - mu; q += d[j] * d[j]; }
        q = wsum(q);
        float rstd = rsqrtf(q * (1.f / 128.f) + 1e-5f);
#pragma unroll
        for (int j = 0; j < 4; j++) {
            float nv = d[j] * rstd * vg1[c0 + j] + vbe1[c0 + j];
            ht[(c0 + j) * 36 + r0 + r] = gelu_f(nv);
        }
    }
    __syncwarp();

    // GEMM2: out[32][128] = gelu(h) @ W2
    float acc2[4][4];
#pragma unroll
    for (int r = 0; r < 4; r++)
#pragma unroll
        for (int j = 0; j < 4; j++) acc2[r][j] = 0.f;

#pragma unroll 8
    for (int k = 0; k < D_; k++) {
        float4 av = *(float4*)&ht[k * 36 + r0];
        float4 wv = *(float4*)&W2s[k * D_ + c0];
        float a[4] = {av.x, av.y, av.z, av.w};
        float w[4] = {wv.x, wv.y, wv.z, wv.w};
#pragma unroll
        for (int r = 0; r < 4; r++)
#pragma unroll
            for (int j = 0; j < 4; j++)
                acc2[r][j] = fmaf(a[r], w[j], acc2[r][j]);
    }
    // +b2, LN2 -> emb ; e_dot epilogue for both layers
#pragma unroll
    for (int r = 0; r < 4; r++) {
        float v[4];
#pragma unroll
        for (int j = 0; j < 4; j++) v[j] = acc2[r][j] + vb2[c0 + j];
        float s = wsum(v[0] + v[1] + v[2] + v[3]);
        float mu = s * (1.f / 128.f);
        float d[4], q = 0.f;
#pragma unroll
        for (int j = 0; j < 4; j++) { d[j] = v[j] - mu; q += d[j] * d[j]; }
        q = wsum(q);
        float rstd = rsqrtf(q * (1.f / 128.f) + 1e-5f);
        float y[4];
#pragma unroll
        for (int j = 0; j < 4; j++)
            y[j] = d[j] * rstd * vg2[c0 + j] + vbe2[c0 + j];

        size_t row = (size_t)b * E_ + e0 + r0 + r;
        *(float4*)&g_emb[row * D_ + c0] = make_float4(y[0], y[1], y[2], y[3]);

        float p1 = 0.f, p2 = 0.f;
#pragma unroll
        for (int j = 0; j < 4; j++) {
            p1 = fmaf(y[j], we1[c0 + j], p1);
            p2 = fmaf(y[j], we2[c0 + j], p2);
        }
        p1 = wsum(p1);
        p2 = wsum(p2);
        if (lane == 0) {
            g_edot[0][row] = p1;
            g_edot[1][row] = p2;
        }
    }
}

// ---------------- message passing (one warp per (batch, node)) ----------------
__global__ void mp_kernel(const float* __restrict__ watt,
                          const float* __restrict__ batt_p, int layer)
{
    int w = (blockIdx.x * blockDim.x + threadIdx.x) >> 5;
    int lane = threadIdx.x & 31;
    if (w >= B_ * N_) return;
    int b = w / N_, n = w % N_;

    const float* node_in = g_nodeA;                 // only read when layer==1
    float* node_out = (layer == 0) ? g_nodeA : g_nodeB;

    float batt = batt_p[0];
    float hd = 0.f;
    float4 cur = make_float4(0.f, 0.f, 0.f, 0.f);
    size_t nrow = ((size_t)b * N_ + n) * D_ + lane * 4;
    if (layer > 0) {
        cur = *(const float4*)&node_in[nrow];
        float4 wh = *(const float4*)&watt[lane * 4];
        float p = cur.x * wh.x + cur.y * wh.y + cur.z * wh.z + cur.w * wh.w;
        hd = wsum(p);
    }

    int start = g_off[n], end = g_off[n + 1];
    int deg = end - start;
    if (deg == 0) {                       // where(deg>0, new, node_b)
        *(float4*)&node_out[nrow] = cur;  // layer0: zeros; layer1: pass-through
        return;
    }

    const float* edot = &g_edot[layer][(size_t)b * E_];

    float m = -1e30f;
    for (int i = start + lane; i < end; i += 32) {
        float s = hd + edot[g_adj[i]] + batt;
        s = (s > 0.f) ? s : 0.2f * s;
        m = fmaxf(m, s);
    }
    m = wmax(m);

    float den = 0.f;
    for (int i = start + lane; i < end; i += 32) {
        float s = hd + edot[g_adj[i]] + batt;
        s = (s > 0.f) ? s : 0.2f * s;
        den += expf(s - m);
    }
    den = wsum(den);

    float4 acc = make_float4(0.f, 0.f, 0.f, 0.f);
    for (int i = start; i < end; i++) {
        int e = g_adj[i];
        float s = hd + edot[e] + batt;
        s = (s > 0.f) ? s : 0.2f * s;
        float p = expf(s - m);
        const float4 v = *(const float4*)&g_emb[((size_t)b * E_ + e) * D_ + lane * 4];
        acc.x = fmaf(p, v.x, acc.x);
        acc.y = fmaf(p, v.y, acc.y);
        acc.z = fmaf(p, v.z, acc.z);
        acc.w = fmaf(p, v.w, acc.w);
    }
    float inv = 1.f / den;
    float4 outv;
    outv.x = gelu_f(acc.x * inv);
    outv.y = gelu_f(acc.y * inv);
    outv.z = gelu_f(acc.z * inv);
    outv.w = gelu_f(acc.w * inv);
    *(float4*)&node_out[nrow] = outv;
}

// ---------------- tensor-core decoder (split-tf32, 3-pass) ----------------
// Block: 256 thr, 64 edge rows. GEMM1: cat[64][384] @ W1[384][256] -> z1
// GEMM2: z1[64][256] @ W2[256][128] -> z2; epilogue dot with w3.
// smem floats:
//   catBuf [64][36]           @ 0      (2304)
//   wBuf   hi[32][264]+lo     @ 2304   (16896)  (GEMM2: hi[32][136]+lo)
//   z1Buf  [64][260]          @ 19200  (16640)
//   b1s 256 @35840 | b2s 128 @36096 | w3s 128 @36224 | part 128 @36352
//   sn 64 @36480 | dn 64 @36544  -> total 36608 floats (146 KB)
#define DEC_SMEM_FLOATS 36608
#define CAT_STR 36
#define W1_STR  264
#define W2_STR  136
#define Z1_STR  260

__global__ void __launch_bounds__(256, 1) decoder_kernel(
    const float* __restrict__ b1, const float* __restrict__ b2,
    const float* __restrict__ w3, const float* __restrict__ b3,
    const int* __restrict__ src, const int* __restrict__ dst,
    float* __restrict__ out)
{
    extern __shared__ float sm[];
    float* catBuf = sm;
    float* wHi    = sm + 2304;
    float* wLo    = sm + 2304 + 32 * W1_STR;       // 10752
    float* w2Hi   = sm + 2304;
    float* w2Lo   = sm + 2304 + 32 * W2_STR;       // 6656
    float* z1Buf  = sm + 19200;
    float* b1s    = sm + 35840;
    float* b2s    = sm + 36096;
    float* w3s    = sm + 36224;
    float* part   = sm + 36352;                    // [2][64]
    int*   sn     = (int*)(sm + 36480);
    int*   dn     = (int*)(sm + 36544);

    int tid  = threadIdx.x;
    int lane = tid & 31;
    int warp = tid >> 5;
    int gid  = lane >> 2;       // group id (row within frag)
    int tig  = lane & 3;        // thread in group (col within frag)
    int b    = blockIdx.y;
    int e0   = blockIdx.x * 64;

    if (tid < 64) { sn[tid] = src[e0 + tid]; dn[tid] = dst[e0 + tid]; }
    b1s[tid] = b1[tid];
    if (tid < 128) { b2s[tid] = b2[tid]; w3s[tid] = w3[tid]; }

    const float* nodeb = g_nodeB + (size_t)b * N_ * D_;
    const float* embb  = g_emb   + (size_t)b * E_ * D_;

    // ---------- GEMM1: warp tile 32x64 (wm: 2 m-tiles, wn: 4 n-tiles) ----------
    int wm = warp & 1;          // m32 tile
    int wn = warp >> 1;         // n64 tile
    int m0 = wm * 32;
    int n0 = wn * 64;

    float acc[2][8][4];
#pragma unroll
    for (int mf = 0; mf < 2; mf++)
#pragma unroll
        for (int nf = 0; nf < 8; nf++)
#pragma unroll
            for (int j = 0; j < 4; j++) acc[mf][nf][j] = 0.f;

    for (int kc = 0; kc < 384; kc += 32) {
        __syncthreads();
        // stage cat chunk [64][32] (gathered), float4 granularity
        for (int i = tid; i < 512; i += 256) {
            int r = i >> 3, q = (i & 7) * 4;
            float4 v;
            if (kc < 128)      v = *(const float4*)&nodeb[(size_t)sn[r] * D_ + kc + q];
            else if (kc < 256) v = *(const float4*)&nodeb[(size_t)dn[r] * D_ + kc - 128 + q];
            else               v = *(const float4*)&embb[(size_t)(e0 + r) * D_ + kc - 256 + q];
            *(float4*)&catBuf[r * CAT_STR + q] = v;
        }
        // stage W1 hi/lo chunk [32][256]
        for (int i = tid; i < 2048; i += 256) {
            int r = i >> 6, q = (i & 63) * 4;
            *(float4*)&wHi[r * W1_STR + q] = *(const float4*)&g_w1hi[(kc + r) * 256 + q];
            *(float4*)&wLo[r * W1_STR + q] = *(const float4*)&g_w1lo[(kc + r) * 256 + q];
        }
        __syncthreads();

#pragma unroll
        for (int kk = 0; kk < 32; kk += 8) {
            // A frags (fp32 -> split in regs)
            uint32_t ah[2][4], al[2][4];
#pragma unroll
            for (int mf = 0; mf < 2; mf++) {
                int rlo = m0 + mf * 16 + gid;
                float a0 = catBuf[rlo * CAT_STR + kk + tig];
                float a1 = catBuf[(rlo + 8) * CAT_STR + kk + tig];
                float a2 = catBuf[rlo * CAT_STR + kk + tig + 4];
                float a3 = catBuf[(rlo + 8) * CAT_STR + kk + tig + 4];
                ah[mf][0] = f2tf32(a0); al[mf][0] = f2tf32(a0 - __uint_as_float(ah[mf][0]));
                ah[mf][1] = f2tf32(a1); al[mf][1] = f2tf32(a1 - __uint_as_float(ah[mf][1]));
                ah[mf][2] = f2tf32(a2); al[mf][2] = f2tf32(a2 - __uint_as_float(ah[mf][2]));
                ah[mf][3] = f2tf32(a3); al[mf][3] = f2tf32(a3 - __uint_as_float(ah[mf][3]));
            }
            // B frags (pre-split)
            uint32_t bh[8][2], bl[8][2];
#pragma unroll
            for (int nf = 0; nf < 8; nf++) {
                int n = n0 + nf * 8 + gid;
                bh[nf][0] = __float_as_uint(wHi[(kk + tig) * W1_STR + n]);
                bh[nf][1] = __float_as_uint(wHi[(kk + tig + 4) * W1_STR + n]);
                bl[nf][0] = __float_as_uint(wLo[(kk + tig) * W1_STR + n]);
                bl[nf][1] = __float_as_uint(wLo[(kk + tig + 4) * W1_STR + n]);
            }
#pragma unroll
            for (int mf = 0; mf < 2; mf++)
#pragma unroll
                for (int nf = 0; nf < 8; nf++) {
                    mma_tf32(acc[mf][nf], ah[mf][0], ah[mf][1], ah[mf][2], ah[mf][3],
                             bh[nf][0], bh[nf][1]);
                    mma_tf32(acc[mf][nf], al[mf][0], al[mf][1], al[mf][2], al[mf][3],
                             bh[nf][0], bh[nf][1]);
                    mma_tf32(acc[mf][nf], ah[mf][0], ah[mf][1], ah[mf][2], ah[mf][3],
                             bl[nf][0], bl[nf][1]);
                }
        }
    }

    // epilogue GEMM1: bias + gelu -> z1Buf
    __syncthreads();
#pragma unroll
    for (int mf = 0; mf < 2; mf++) {
        int rlo = m0 + mf * 16 + gid;
#pragma unroll
        for (int nf = 0; nf < 8; nf++) {
            int c0i = n0 + nf * 8 + 2 * tig;
            float v0 = gelu_f(acc[mf][nf][0] + b1s[c0i]);
            float v1 = gelu_f(acc[mf][nf][1] + b1s[c0i + 1]);
            float v2 = gelu_f(acc[mf][nf][2] + b1s[c0i]);
            float v3 = gelu_f(acc[mf][nf][3] + b1s[c0i + 1]);
            *(float2*)&z1Buf[rlo * Z1_STR + c0i]       = make_float2(v0, v1);
            *(float2*)&z1Buf[(rlo + 8) * Z1_STR + c0i] = make_float2(v2, v3);
        }
    }

    // ---------- GEMM2: warp tile 16x64 (wm2: 4 m-tiles, wn2: 2 n-tiles) ----------
    int wm2 = warp & 3;
    int wn2 = warp >> 2;
    int m20 = wm2 * 16;
    int n20 = wn2 * 64;

    float acc2[8][4];
#pragma unroll
    for (int nf = 0; nf < 8; nf++)
#pragma unroll
        for (int j = 0; j < 4; j++) acc2[nf][j] = 0.f;

    for (int kc = 0; kc < 256; kc += 32) {
        __syncthreads();
        for (int i = tid; i < 1024; i += 256) {
            int r = i >> 5, q = (i & 31) * 4;
            *(float4*)&w2Hi[r * W2_STR + q] = *(const float4*)&g_w2hi[(kc + r) * 128 + q];
            *(float4*)&w2Lo[r * W2_STR + q] = *(const float4*)&g_w2lo[(kc + r) * 128 + q];
        }
        __syncthreads();

#pragma unroll
        for (int kk = 0; kk < 32; kk += 8) {
            int rlo = m20 + gid;
            float a0 = z1Buf[rlo * Z1_STR + kc + kk + tig];
            float a1 = z1Buf[(rlo + 8) * Z1_STR + kc + kk + tig];
            float a2 = z1Buf[rlo * Z1_STR + kc + kk + tig + 4];
            float a3 = z1Buf[(rlo + 8) * Z1_STR + kc + kk + tig + 4];
            uint32_t ah0 = f2tf32(a0), al0 = f2tf32(a0 - __uint_as_float(ah0));
            uint32_t ah1 = f2tf32(a1), al1 = f2tf32(a1 - __uint_as_float(ah1));
            uint32_t ah2 = f2tf32(a2), al2 = f2tf32(a2 - __uint_as_float(ah2));
            uint32_t ah3 = f2tf32(a3), al3 = f2tf32(a3 - __uint_as_float(ah3));

#pragma unroll
            for (int nf = 0; nf < 8; nf++) {
                int n = n20 + nf * 8 + gid;
                uint32_t b0 = __float_as_uint(w2Hi[(kk + tig) * W2_STR + n]);
                uint32_t b1r = __float_as_uint(w2Hi[(kk + tig + 4) * W2_STR + n]);
                uint32_t c0r = __float_as_uint(w2Lo[(kk + tig) * W2_STR + n]);
                uint32_t c1r = __float_as_uint(w2Lo[(kk + tig + 4) * W2_STR + n]);
                mma_tf32(acc2[nf], ah0, ah1, ah2, ah3, b0, b1r);
                mma_tf32(acc2[nf], al0, al1, al2, al3, b0, b1r);
                mma_tf32(acc2[nf], ah0, ah1, ah2, ah3, c0r, c1r);
            }
        }
    }

    // epilogue: gelu(z2 + b2) . w3, reduce over n
    float plo = 0.f, phi = 0.f;
#pragma unroll
    for (int nf = 0; nf < 8; nf++) {
        int c0i = n20 + nf * 8 + 2 * tig;
        float u0 = gelu_f(acc2[nf][0] + b2s[c0i]) * w3s[c0i];
        float u1 = gelu_f(acc2[nf][1] + b2s[c0i + 1]) * w3s[c0i + 1];
        float u2 = gelu_f(acc2[nf][2] + b2s[c0i]) * w3s[c0i];
        float u3 = gelu_f(acc2[nf][3] + b2s[c0i + 1]) * w3s[c0i + 1];
        plo += u0 + u1;
        phi += u2 + u3;
    }
    // reduce across tig (lanes xor 1,2 within each group of 4)
    plo += __shfl_xor_sync(0xffffffffu, plo, 1);
    plo += __shfl_xor_sync(0xffffffffu, plo, 2);
    phi += __shfl_xor_sync(0xffffffffu, phi, 1);
    phi += __shfl_xor_sync(0xffffffffu, phi, 2);
    __syncthreads();
    if (tig == 0) {
        part[wn2 * 64 + m20 + gid]     = plo;
        part[wn2 * 64 + m20 + gid + 8] = phi;
    }
    __syncthreads();
    if (tid < 64) {
        out[(size_t)b * E_ + e0 + tid] = part[tid] + part[64 + tid] + b3[0];
    }
}

// ---------------- launch ----------------
extern "C" void kernel_launch(void* const* d_in, const int* in_sizes, int n_in,
                              void* d_out, int out_size)
{
    const float* edge_features = (const float*)d_in[0];
    const float* enc_w1  = (const float*)d_in[1];
    const float* enc_b1  = (const float*)d_in[2];
    const float* enc_g1  = (const float*)d_in[3];
    const float* enc_be1 = (const float*)d_in[4];
    const float* enc_w2  = (const float*)d_in[5];
    const float* enc_b2  = (const float*)d_in[6];
    const float* enc_g2  = (const float*)d_in[7];
    const float* enc_be2 = (const float*)d_in[8];
    const float* watt1   = (const float*)d_in[9];
    const float* batt1   = (const float*)d_in[10];
    const float* watt2   = (const float*)d_in[11];
    const float* batt2   = (const float*)d_in[12];
    const float* dec_w1  = (const float*)d_in[13];
    const float* dec_b1  = (const float*)d_in[14];
    const float* dec_w2  = (const float*)d_in[15];
    const float* dec_b2  = (const float*)d_in[16];
    const float* dec_w3  = (const float*)d_in[17];
    const float* dec_b3  = (const float*)d_in[18];
    const int*   src     = (const int*)d_in[19];
    const int*   dst     = (const int*)d_in[20];
    float* out = (float*)d_out;

    cudaFuncSetAttribute(encoder_kernel, cudaFuncAttributeMaxDynamicSharedMemorySize,
                         ENC_SMEM_FLOATS * 4);
    cudaFuncSetAttribute(decoder_kernel, cudaFuncAttributeMaxDynamicSharedMemorySize,
                         DEC_SMEM_FLOATS * 4);

    // weight split for tensor-core decoder (overlaps with CSR/encoder work)
    split_weights_kernel<<<(384 * 256 + 256 * 128 + 255) / 256, 256>>>(dec_w1, dec_w2);

    // CSR build (recomputed every call; deterministic work)
    zero_cnt_kernel<<<(N_ + 255) / 256, 256>>>();
    count_kernel<<<(P2E_ + 255) / 256, 256>>>(src, dst);
    scan_kernel<<<1, 1024>>>();
    fill_kernel<<<(P2E_ + 255) / 256, 256>>>(src, dst);

    // fused encoder (+ e_dot epilogues for both attention layers)
    encoder_kernel<<<dim3(E_ / 32, B_), 256, ENC_SMEM_FLOATS * 4>>>(
        edge_features, enc_w1, enc_b1, enc_g1, enc_be1,
        enc_w2, enc_b2, enc_g2, enc_be2, watt1, watt2);

    // message passing: layer 1 (node_in = 0), layer 2
    int mp_blocks = (B_ * N_ + 7) / 8;   // 8 warps/block
    mp_kernel<<<mp_blocks, 256>>>(watt1, batt1, 0);
    mp_kernel<<<mp_blocks, 256>>>(watt2, batt2, 1);

    // tensor-core decoder MLP
    decoder_kernel<<<dim3(E_ / 64, B_), 256, DEC_SMEM_FLOATS * 4>>>(
        dec_b1, dec_b2, dec_w3, dec_b3, src, dst, out);
}

// round 3
// speedup vs baseline: 2.0417x; 1.7561x over previous
#include <cuda_runtime.h>
#include <cuda_bf16.h>
#include <cstdint>
#include <cstddef>
#include <math.h>

// Problem constants (fixed dataset)
#define B_   2
#define E_   160000
#define N_   10000
#define FIN_ 24
#define D_   128
#define P2E_ (2 * E_)

// ---------------- scratch (static __device__, no allocations) ----------------
__device__ float g_emb[(size_t)B_ * E_ * D_];     // edge embeddings [B][E][128]
__device__ float g_edot[2][(size_t)B_ * E_];      // per-layer e_pair . watt[128:256]
__device__ float g_nodeA[(size_t)B_ * N_ * D_];   // node emb after layer 1
__device__ float g_nodeB[(size_t)B_ * N_ * D_];   // node emb after layer 2
__device__ int   g_cnt[N_];
__device__ int   g_cur[N_];
__device__ int   g_off[N_ + 1];
__device__ int   g_adj[P2E_];
// bf16 hi/lo split decoder weights, pre-packed in m16n8k16 B-fragment order
__device__ __align__(16) __nv_bfloat16 g_w1ph[384 * 256];
__device__ __align__(16) __nv_bfloat16 g_w1pl[384 * 256];
__device__ __align__(16) __nv_bfloat16 g_w2ph[256 * 128];
__device__ __align__(16) __nv_bfloat16 g_w2pl[256 * 128];

// ---------------- helpers ----------------
__device__ __forceinline__ float gelu_f(float x) {
    return 0.5f * x * (1.0f + erff(x * 0.70710678118654752f));
}
__device__ __forceinline__ float wsum(float v) {
#pragma unroll
    for (int o = 16; o; o >>= 1) v += __shfl_xor_sync(0xffffffffu, v, o);
    return v;
}
__device__ __forceinline__ float wmax(float v) {
#pragma unroll
    for (int o = 16; o; o >>= 1) v = fmaxf(v, __shfl_xor_sync(0xffffffffu, v, o));
    return v;
}
__device__ __forceinline__ uint32_t s2u(const void* p) {
    return (uint32_t)__cvta_generic_to_shared(p);
}
__device__ __forceinline__ void cpa16(uint32_t dst, const void* src) {
    asm volatile("cp.async.cg.shared.global [%0], [%1], 16;" :: "r"(dst), "l"(src));
}
__device__ __forceinline__ void cpa_commit_wait() {
    asm volatile("cp.async.commit_group;\n\tcp.async.wait_group 0;" ::: "memory");
}
#define LDMX4(r, addr) \
    asm volatile("ldmatrix.sync.aligned.m8n8.x4.shared.b16 {%0,%1,%2,%3}, [%4];" \
        : "=r"((r)[0]), "=r"((r)[1]), "=r"((r)[2]), "=r"((r)[3]) : "r"(addr))

__device__ __forceinline__ void mma_bf16(float* c, const uint32_t* a,
                                         uint32_t b0, uint32_t b1) {
    asm volatile(
        "mma.sync.aligned.m16n8k16.row.col.f32.bf16.bf16.f32 "
        "{%0,%1,%2,%3},{%4,%5,%6,%7},{%8,%9},{%0,%1,%2,%3};"
        : "+f"(c[0]), "+f"(c[1]), "+f"(c[2]), "+f"(c[3])
        : "r"(a[0]), "r"(a[1]), "r"(a[2]), "r"(a[3]), "r"(b0), "r"(b1));
}

// ---------------- weight pack prep (bf16 hi/lo, B-fragment order) ----------------
// Packed layout: for k16 slice s, col n, tig t, elem j in {2t,2t+1,2t+8,2t+9}:
//   dst[((s*NC + n)*4 + t)*4 + j]
__global__ void pack_weights_kernel(const float* __restrict__ w1,
                                    const float* __restrict__ w2) {
    int i = blockIdx.x * blockDim.x + threadIdx.x;
    if (i < 384 * 256) {
        int j = i & 3, t = (i >> 2) & 3, n = (i >> 4) & 255, s = i >> 12;
        int k = s * 16 + 2 * t + (j & 1) + ((j >> 1) << 3);
        float x = w1[k * 256 + n];
        __nv_bfloat16 h = __float2bfloat16_rn(x);
        g_w1ph[i] = h;
        g_w1pl[i] = __float2bfloat16_rn(x - __bfloat162float(h));
    }
    int i2 = i - 384 * 256;
    if (i2 >= 0 && i2 < 256 * 128) {
        int j = i2 & 3, t = (i2 >> 2) & 3, n = (i2 >> 4) & 127, s = i2 >> 11;
        int k = s * 16 + 2 * t + (j & 1) + ((j >> 1) << 3);
        float x = w2[k * 128 + n];
        __nv_bfloat16 h = __float2bfloat16_rn(x);
        g_w2ph[i2] = h;
        g_w2pl[i2] = __float2bfloat16_rn(x - __bfloat162float(h));
    }
}

// ---------------- CSR build ----------------
__global__ void zero_cnt_kernel() {
    int i = blockIdx.x * blockDim.x + threadIdx.x;
    if (i < N_) g_cnt[i] = 0;
}

__global__ void count_kernel(const int* __restrict__ src, const int* __restrict__ dst) {
    int idx = blockIdx.x * blockDim.x + threadIdx.x;
    if (idx >= P2E_) return;
    int node = (idx < E_) ? src[idx] : dst[idx - E_];
    atomicAdd(&g_cnt[node], 1);
}

__global__ void scan_kernel() {
    __shared__ int ss[1024];
    int t = threadIdx.x;
    int base = t * 10;                  // 1024*10 >= N_
    int s = 0;
#pragma unroll
    for (int i = 0; i < 10; i++) {
        int idx = base + i;
        if (idx < N_) s += g_cnt[idx];
    }
    ss[t] = s;
    __syncthreads();
    for (int off = 1; off < 1024; off <<= 1) {
        int v = (t >= off) ? ss[t - off] : 0;
        __syncthreads();
        ss[t] += v;
        __syncthreads();
    }
    int run = (t > 0) ? ss[t - 1] : 0;
#pragma unroll
    for (int i = 0; i < 10; i++) {
        int idx = base + i;
        if (idx < N_) {
            g_off[idx] = run;
            run += g_cnt[idx];
            g_cur[idx] = 0;
        }
    }
    if (t == 1023) g_off[N_] = ss[1023];
}

__global__ void fill_kernel(const int* __restrict__ src, const int* __restrict__ dst) {
    int idx = blockIdx.x * blockDim.x + threadIdx.x;
    if (idx >= P2E_) return;
    int node = (idx < E_) ? src[idx] : dst[idx - E_];
    int e    = (idx < E_) ? idx : idx - E_;
    int pos = g_off[node] + atomicAdd(&g_cur[node], 1);
    g_adj[pos] = e;
}

// ---------------- fused edge encoder ----------------
#define ENC_SMEM_FLOATS 25856
__global__ void __launch_bounds__(256, 2) encoder_kernel(
    const float* __restrict__ xin,
    const float* __restrict__ w1, const float* __restrict__ b1,
    const float* __restrict__ g1, const float* __restrict__ be1,
    const float* __restrict__ w2, const float* __restrict__ b2,
    const float* __restrict__ g2, const float* __restrict__ be2,
    const float* __restrict__ watt1, const float* __restrict__ watt2)
{
    extern __shared__ float sm[];
    float* W1s  = sm;
    float* W2s  = sm + 3072;
    float* xs   = sm + 19456;
    float* ht   = sm + 20224;   // [128][36] transposed h
    float* vb1  = sm + 24832;
    float* vg1  = sm + 24960;
    float* vbe1 = sm + 25088;
    float* vb2  = sm + 25216;
    float* vg2  = sm + 25344;
    float* vbe2 = sm + 25472;
    float* we1  = sm + 25600;
    float* we2  = sm + 25728;

    int tid = threadIdx.x;
    int b = blockIdx.y;
    int e0 = blockIdx.x * 32;

    for (int i = tid; i < FIN_ * D_; i += 256) W1s[i] = w1[i];
    for (int i = tid; i < D_ * D_; i += 256)   W2s[i] = w2[i];
    if (tid < 128) {
        vb1[tid] = b1[tid];  vg1[tid] = g1[tid];  vbe1[tid] = be1[tid];
        vb2[tid] = b2[tid];  vg2[tid] = g2[tid];  vbe2[tid] = be2[tid];
        we1[tid] = watt1[128 + tid];
        we2[tid] = watt2[128 + tid];
    }
    {
        size_t base = ((size_t)b * E_ + e0) * FIN_;
        for (int i = tid; i < 32 * FIN_; i += 256) xs[i] = xin[base + i];
    }
    __syncthreads();

    int warp = tid >> 5, lane = tid & 31;
    int r0 = warp * 4;
    int c0 = lane * 4;

    // GEMM1: h[32][128] = x[32][24] @ W1
    float acc[4][4];
#pragma unroll
    for (int r = 0; r < 4; r++)
#pragma unroll
        for (int j = 0; j < 4; j++) acc[r][j] = 0.f;

#pragma unroll
    for (int k = 0; k < FIN_; k++) {
        float4 wv = *(float4*)&W1s[k * D_ + c0];
#pragma unroll
        for (int r = 0; r < 4; r++) {
            float a = xs[(r0 + r) * FIN_ + k];
            acc[r][0] = fmaf(a, wv.x, acc[r][0]);
            acc[r][1] = fmaf(a, wv.y, acc[r][1]);
            acc[r][2] = fmaf(a, wv.z, acc[r][2]);
            acc[r][3] = fmaf(a, wv.w, acc[r][3]);
        }
    }
    // +b1, LN1, gelu -> ht (transposed)
#pragma unroll
    for (int r = 0; r < 4; r++) {
        float v[4];
#pragma unroll
        for (int j = 0; j < 4; j++) v[j] = acc[r][j] + vb1[c0 + j];
        float s = wsum(v[0] + v[1] + v[2] + v[3]);
        float mu = s * (1.f / 128.f);
        float d[4], q = 0.f;
#pragma unroll
        for (int j = 0; j < 4; j++) { d[j] = v[j] - mu; q += d[j] * d[j]; }
        q = wsum(q);
        float rstd = rsqrtf(q * (1.f / 128.f) + 1e-5f);
#pragma unroll
        for (int j = 0; j < 4; j++) {
            float nv = d[j] * rstd * vg1[c0 + j] + vbe1[c0 + j];
            ht[(c0 + j) * 36 + r0 + r] = gelu_f(nv);
        }
    }
    __syncwarp();

    // GEMM2: out[32][128] = gelu(h) @ W2
    float acc2[4][4];
#pragma unroll
    for (int r = 0; r < 4; r++)
#pragma unroll
        for (int j = 0; j < 4; j++) acc2[r][j] = 0.f;

#pragma unroll 8
    for (int k = 0; k < D_; k++) {
        float4 av = *(float4*)&ht[k * 36 + r0];
        float4 wv = *(float4*)&W2s[k * D_ + c0];
        float a[4] = {av.x, av.y, av.z, av.w};
        float w[4] = {wv.x, wv.y, wv.z, wv.w};
#pragma unroll
        for (int r = 0; r < 4; r++)
#pragma unroll
            for (int j = 0; j < 4; j++)
                acc2[r][j] = fmaf(a[r], w[j], acc2[r][j]);
    }
    // +b2, LN2 -> emb ; e_dot epilogue for both layers
#pragma unroll
    for (int r = 0; r < 4; r++) {
        float v[4];
#pragma unroll
        for (int j = 0; j < 4; j++) v[j] = acc2[r][j] + vb2[c0 + j];
        float s = wsum(v[0] + v[1] + v[2] + v[3]);
        float mu = s * (1.f / 128.f);
        float d[4], q = 0.f;
#pragma unroll
        for (int j = 0; j < 4; j++) { d[j] = v[j] - mu; q += d[j] * d[j]; }
        q = wsum(q);
        float rstd = rsqrtf(q * (1.f / 128.f) + 1e-5f);
        float y[4];
#pragma unroll
        for (int j = 0; j < 4; j++)
            y[j] = d[j] * rstd * vg2[c0 + j] + vbe2[c0 + j];

        size_t row = (size_t)b * E_ + e0 + r0 + r;
        *(float4*)&g_emb[row * D_ + c0] = make_float4(y[0], y[1], y[2], y[3]);

        float p1 = 0.f, p2 = 0.f;
#pragma unroll
        for (int j = 0; j < 4; j++) {
            p1 = fmaf(y[j], we1[c0 + j], p1);
            p2 = fmaf(y[j], we2[c0 + j], p2);
        }
        p1 = wsum(p1);
        p2 = wsum(p2);
        if (lane == 0) {
            g_edot[0][row] = p1;
            g_edot[1][row] = p2;
        }
    }
}

// ---------------- message passing (one warp per (batch, node)) ----------------
__global__ void mp_kernel(const float* __restrict__ watt,
                          const float* __restrict__ batt_p, int layer)
{
    int w = (blockIdx.x * blockDim.x + threadIdx.x) >> 5;
    int lane = threadIdx.x & 31;
    if (w >= B_ * N_) return;
    int b = w / N_, n = w % N_;

    const float* node_in = g_nodeA;                 // only read when layer==1
    float* node_out = (layer == 0) ? g_nodeA : g_nodeB;

    float batt = batt_p[0];
    float hd = 0.f;
    float4 cur = make_float4(0.f, 0.f, 0.f, 0.f);
    size_t nrow = ((size_t)b * N_ + n) * D_ + lane * 4;
    if (layer > 0) {
        cur = *(const float4*)&node_in[nrow];
        float4 wh = *(const float4*)&watt[lane * 4];
        float p = cur.x * wh.x + cur.y * wh.y + cur.z * wh.z + cur.w * wh.w;
        hd = wsum(p);
    }

    int start = g_off[n], end = g_off[n + 1];
    int deg = end - start;
    if (deg == 0) {                       // where(deg>0, new, node_b)
        *(float4*)&node_out[nrow] = cur;  // layer0: zeros; layer1: pass-through
        return;
    }

    const float* edot = &g_edot[layer][(size_t)b * E_];

    float m = -1e30f;
    for (int i = start + lane; i < end; i += 32) {
        float s = hd + edot[g_adj[i]] + batt;
        s = (s > 0.f) ? s : 0.2f * s;
        m = fmaxf(m, s);
    }
    m = wmax(m);

    float den = 0.f;
    for (int i = start + lane; i < end; i += 32) {
        float s = hd + edot[g_adj[i]] + batt;
        s = (s > 0.f) ? s : 0.2f * s;
        den += expf(s - m);
    }
    den = wsum(den);

    float4 acc = make_float4(0.f, 0.f, 0.f, 0.f);
    for (int i = start; i < end; i++) {
        int e = g_adj[i];
        float s = hd + edot[e] + batt;
        s = (s > 0.f) ? s : 0.2f * s;
        float p = expf(s - m);
        const float4 v = *(const float4*)&g_emb[((size_t)b * E_ + e) * D_ + lane * 4];
        acc.x = fmaf(p, v.x, acc.x);
        acc.y = fmaf(p, v.y, acc.y);
        acc.z = fmaf(p, v.z, acc.z);
        acc.w = fmaf(p, v.w, acc.w);
    }
    float inv = 1.f / den;
    float4 outv;
    outv.x = gelu_f(acc.x * inv);
    outv.y = gelu_f(acc.y * inv);
    outv.z = gelu_f(acc.z * inv);
    outv.w = gelu_f(acc.w * inv);
    *(float4*)&node_out[nrow] = outv;
}

// ---------------- tensor-core decoder (bf16 split, 3-product) ----------------
// Block: 256 thr, 64 edge rows, 2 CTAs/SM.
// smem bytes:
//   bHi    @ 0       16384   (packed W chunk hi: 2(G1)/4(G2) k16-slices)
//   bLo    @ 16384   16384
//   catHi  @ 32768    5120   (bf16 [64][40], ldmatrix stride 80B)
//   catLo  @ 37888    5120
//   z1Hi   @ 43008   33792   (bf16 [64][264], ldmatrix stride 528B)
//   z1Lo   @ 76800   33792
//   b1s    @ 110592   1024
//   b2s    @ 111616    512
//   w3s    @ 112128    512
//   part   @ 112640    512
//   sn     @ 113152    256
//   dn     @ 113408    256   -> total 113664
#define DEC_SMEM_BYTES 113664

__global__ void __launch_bounds__(256, 2) decoder_kernel(
    const float* __restrict__ b1, const float* __restrict__ b2,
    const float* __restrict__ w3, const float* __restrict__ b3,
    const int* __restrict__ src, const int* __restrict__ dst,
    float* __restrict__ out)
{
    extern __shared__ char smraw[];
    __nv_bfloat16* bHi   = (__nv_bfloat16*)(smraw);
    __nv_bfloat16* bLo   = (__nv_bfloat16*)(smraw + 16384);
    __nv_bfloat16* catHi = (__nv_bfloat16*)(smraw + 32768);
    __nv_bfloat16* catLo = (__nv_bfloat16*)(smraw + 37888);
    __nv_bfloat16* z1Hi  = (__nv_bfloat16*)(smraw + 43008);
    __nv_bfloat16* z1Lo  = (__nv_bfloat16*)(smraw + 76800);
    float* b1s  = (float*)(smraw + 110592);
    float* b2s  = (float*)(smraw + 111616);
    float* w3s  = (float*)(smraw + 112128);
    float* part = (float*)(smraw + 112640);
    int*   sn   = (int*)(smraw + 113152);
    int*   dn   = (int*)(smraw + 113408);

    int tid  = threadIdx.x;
    int lane = tid & 31;
    int warp = tid >> 5;
    int gid  = lane >> 2;
    int tig  = lane & 3;
    int b    = blockIdx.y;
    int e0   = blockIdx.x * 64;

    if (tid < 64) { sn[tid] = src[e0 + tid]; dn[tid] = dst[e0 + tid]; }
    b1s[tid] = b1[tid];
    if (tid < 128) { b2s[tid] = b2[tid]; w3s[tid] = w3[tid]; }

    const float* nodeb = g_nodeB + (size_t)b * N_ * D_;
    const float* embb  = g_emb   + (size_t)b * E_ * D_;

    uint32_t bHiU   = s2u(bHi);
    uint32_t bLoU   = s2u(bLo);
    uint32_t catHiU = s2u(catHi);
    uint32_t catLoU = s2u(catLo);
    uint32_t z1HiU  = s2u(z1Hi);
    uint32_t z1LoU  = s2u(z1Lo);

    int arow  = lane & 15;
    uint32_t ahalf = (lane >> 4) * 16;

    // ---------- GEMM1: warp tile 32x64; wm = warp&1 (m32), wn = warp>>1 (n64) ----------
    int m0 = (warp & 1) * 32;
    int n0 = (warp >> 1) * 64;

    float acc[2][8][4];
#pragma unroll
    for (int mf = 0; mf < 2; mf++)
#pragma unroll
        for (int nf = 0; nf < 8; nf++)
#pragma unroll
            for (int j = 0; j < 4; j++) acc[mf][nf][j] = 0.f;

    for (int kc = 0; kc < 384; kc += 32) {
        __syncthreads();
        // A gather + bf16 hi/lo split -> catHi/catLo
        for (int i = tid; i < 512; i += 256) {
            int r = i >> 3, q = (i & 7) * 4;
            float4 v;
            if (kc < 128)      v = *(const float4*)&nodeb[(size_t)sn[r] * D_ + kc + q];
            else if (kc < 256) v = *(const float4*)&nodeb[(size_t)dn[r] * D_ + kc - 128 + q];
            else               v = *(const float4*)&embb[(size_t)(e0 + r) * D_ + kc - 256 + q];
            __nv_bfloat162 h01 = __floats2bfloat162_rn(v.x, v.y);
            __nv_bfloat162 h23 = __floats2bfloat162_rn(v.z, v.w);
            __nv_bfloat162 l01 = __floats2bfloat162_rn(
                v.x - __bfloat162float(h01.x), v.y - __bfloat162float(h01.y));
            __nv_bfloat162 l23 = __floats2bfloat162_rn(
                v.z - __bfloat162float(h23.x), v.w - __bfloat162float(h23.y));
            int o = r * 40 + q;
            *(__nv_bfloat162*)&catHi[o]     = h01;
            *(__nv_bfloat162*)&catHi[o + 2] = h23;
            *(__nv_bfloat162*)&catLo[o]     = l01;
            *(__nv_bfloat162*)&catLo[o + 2] = l23;
        }
        // B chunk (2 k16 slices, fragment-packed) via cp.async
        {
            const __nv_bfloat16* srcH = g_w1ph + kc * 256;
            const __nv_bfloat16* srcL = g_w1pl + kc * 256;
            for (int i = tid; i < 1024; i += 256) {
                cpa16(bHiU + i * 16, srcH + i * 8);
                cpa16(bLoU + i * 16, srcL + i * 8);
            }
        }
        cpa_commit_wait();
        __syncthreads();

#pragma unroll
        for (int ls = 0; ls < 2; ls++) {
            uint32_t ab = ls * 32 + ahalf;
            uint32_t ah[2][4], al[2][4];
#pragma unroll
            for (int mf = 0; mf < 2; mf++) {
                uint32_t ra = (m0 + mf * 16 + arow) * 80 + ab;
                LDMX4(ah[mf], catHiU + ra);
                LDMX4(al[mf], catLoU + ra);
            }
#pragma unroll
            for (int nf = 0; nf < 8; nf++) {
                int n = n0 + nf * 8 + gid;
                int bo = ls * 4096 + n * 16 + tig * 4;
                uint2 bh = *(const uint2*)(bHi + bo);
                uint2 bl = *(const uint2*)(bLo + bo);
#pragma unroll
                for (int mf = 0; mf < 2; mf++) {
                    mma_bf16(acc[mf][nf], ah[mf], bh.x, bh.y);
                    mma_bf16(acc[mf][nf], al[mf], bh.x, bh.y);
                    mma_bf16(acc[mf][nf], ah[mf], bl.x, bl.y);
                }
            }
        }
    }

    // GEMM1 epilogue: bias + gelu -> z1 (bf16 hi/lo, own-warp tile, no race)
#pragma unroll
    for (int mf = 0; mf < 2; mf++) {
        int rlo = m0 + mf * 16 + gid;
#pragma unroll
        for (int nf = 0; nf < 8; nf++) {
            int c = n0 + nf * 8 + 2 * tig;
            float v0 = gelu_f(acc[mf][nf][0] + b1s[c]);
            float v1 = gelu_f(acc[mf][nf][1] + b1s[c + 1]);
            float v2 = gelu_f(acc[mf][nf][2] + b1s[c]);
            float v3 = gelu_f(acc[mf][nf][3] + b1s[c + 1]);
            __nv_bfloat162 h01 = __floats2bfloat162_rn(v0, v1);
            __nv_bfloat162 h23 = __floats2bfloat162_rn(v2, v3);
            __nv_bfloat162 l01 = __floats2bfloat162_rn(
                v0 - __bfloat162float(h01.x), v1 - __bfloat162float(h01.y));
            __nv_bfloat162 l23 = __floats2bfloat162_rn(
                v2 - __bfloat162float(h23.x), v3 - __bfloat162float(h23.y));
            *(__nv_bfloat162*)&z1Hi[rlo * 264 + c]       = h01;
            *(__nv_bfloat162*)&z1Hi[(rlo + 8) * 264 + c] = h23;
            *(__nv_bfloat162*)&z1Lo[rlo * 264 + c]       = l01;
            *(__nv_bfloat162*)&z1Lo[(rlo + 8) * 264 + c] = l23;
        }
    }

    // ---------- GEMM2: warp tile 16x64; wm2 = warp&3, wn2 = warp>>2 ----------
    int m20 = (warp & 3) * 16;
    int n20 = (warp >> 2) * 64;

    float acc2[8][4];
#pragma unroll
    for (int nf = 0; nf < 8; nf++)
#pragma unroll
        for (int j = 0; j < 4; j++) acc2[nf][j] = 0.f;

    for (int kc = 0; kc < 256; kc += 64) {
        __syncthreads();   // also guards z1 writes (first iter) / bHi reuse
        {
            const __nv_bfloat16* srcH = g_w2ph + kc * 128;
            const __nv_bfloat16* srcL = g_w2pl + kc * 128;
            for (int i = tid; i < 1024; i += 256) {
                cpa16(bHiU + i * 16, srcH + i * 8);
                cpa16(bLoU + i * 16, srcL + i * 8);
            }
        }
        cpa_commit_wait();
        __syncthreads();

#pragma unroll
        for (int ls = 0; ls < 4; ls++) {
            uint32_t ra = (m20 + arow) * 528 + (kc + ls * 16) * 2 + ahalf;
            uint32_t ah[4], al[4];
            LDMX4(ah, z1HiU + ra);
            LDMX4(al, z1LoU + ra);
#pragma unroll
            for (int nf = 0; nf < 8; nf++) {
                int n = n20 + nf * 8 + gid;
                int bo = ls * 2048 + n * 16 + tig * 4;
                uint2 bh = *(const uint2*)(bHi + bo);
                uint2 bl = *(const uint2*)(bLo + bo);
                mma_bf16(acc2[nf], ah, bh.x, bh.y);
                mma_bf16(acc2[nf], al, bh.x, bh.y);
                mma_bf16(acc2[nf], ah, bl.x, bl.y);
            }
        }
    }

    // epilogue: gelu(z2 + b2) . w3, reduce over n
    float plo = 0.f, phi = 0.f;
#pragma unroll
    for (int nf = 0; nf < 8; nf++) {
        int c = n20 + nf * 8 + 2 * tig;
        float u0 = gelu_f(acc2[nf][0] + b2s[c]) * w3s[c];
        float u1 = gelu_f(acc2[nf][1] + b2s[c + 1]) * w3s[c + 1];
        float u2 = gelu_f(acc2[nf][2] + b2s[c]) * w3s[c];
        float u3 = gelu_f(acc2[nf][3] + b2s[c + 1]) * w3s[c + 1];
        plo += u0 + u1;
        phi += u2 + u3;
    }
    plo += __shfl_xor_sync(0xffffffffu, plo, 1);
    plo += __shfl_xor_sync(0xffffffffu, plo, 2);
    phi += __shfl_xor_sync(0xffffffffu, phi, 1);
    phi += __shfl_xor_sync(0xffffffffu, phi, 2);
    __syncthreads();
    if (tig == 0) {
        part[(warp >> 2) * 64 + m20 + gid]     = plo;
        part[(warp >> 2) * 64 + m20 + gid + 8] = phi;
    }
    __syncthreads();
    if (tid < 64) {
        out[(size_t)b * E_ + e0 + tid] = part[tid] + part[64 + tid] + b3[0];
    }
}

// ---------------- launch ----------------
extern "C" void kernel_launch(void* const* d_in, const int* in_sizes, int n_in,
                              void* d_out, int out_size)
{
    const float* edge_features = (const float*)d_in[0];
    const float* enc_w1  = (const float*)d_in[1];
    const float* enc_b1  = (const float*)d_in[2];
    const float* enc_g1  = (const float*)d_in[3];
    const float* enc_be1 = (const float*)d_in[4];
    const float* enc_w2  = (const float*)d_in[5];
    const float* enc_b2  = (const float*)d_in[6];
    const float* enc_g2  = (const float*)d_in[7];
    const float* enc_be2 = (const float*)d_in[8];
    const float* watt1   = (const float*)d_in[9];
    const float* batt1   = (const float*)d_in[10];
    const float* watt2   = (const float*)d_in[11];
    const float* batt2   = (const float*)d_in[12];
    const float* dec_w1  = (const float*)d_in[13];
    const float* dec_b1  = (const float*)d_in[14];
    const float* dec_w2  = (const float*)d_in[15];
    const float* dec_b2  = (const float*)d_in[16];
    const float* dec_w3  = (const float*)d_in[17];
    const float* dec_b3  = (const float*)d_in[18];
    const int*   src     = (const int*)d_in[19];
    const int*   dst     = (const int*)d_in[20];
    float* out = (float*)d_out;

    cudaFuncSetAttribute(encoder_kernel, cudaFuncAttributeMaxDynamicSharedMemorySize,
                         ENC_SMEM_FLOATS * 4);
    cudaFuncSetAttribute(decoder_kernel, cudaFuncAttributeMaxDynamicSharedMemorySize,
                         DEC_SMEM_BYTES);

    // bf16 fragment-packed weight prep
    pack_weights_kernel<<<(384 * 256 + 256 * 128 + 255) / 256, 256>>>(dec_w1, dec_w2);

    // CSR build (recomputed every call; deterministic work)
    zero_cnt_kernel<<<(N_ + 255) / 256, 256>>>();
    count_kernel<<<(P2E_ + 255) / 256, 256>>>(src, dst);
    scan_kernel<<<1, 1024>>>();
    fill_kernel<<<(P2E_ + 255) / 256, 256>>>(src, dst);

    // fused encoder (+ e_dot epilogues for both attention layers)
    encoder_kernel<<<dim3(E_ / 32, B_), 256, ENC_SMEM_FLOATS * 4>>>(
        edge_features, enc_w1, enc_b1, enc_g1, enc_be1,
        enc_w2, enc_b2, enc_g2, enc_be2, watt1, watt2);

    // message passing: layer 1 (node_in = 0), layer 2
    int mp_blocks = (B_ * N_ + 7) / 8;   // 8 warps/block
    mp_kernel<<<mp_blocks, 256>>>(watt1, batt1, 0);
    mp_kernel<<<mp_blocks, 256>>>(watt2, batt2, 1);

    // tensor-core decoder MLP (bf16 split)
    decoder_kernel<<<dim3(E_ / 64, B_), 256, DEC_SMEM_BYTES>>>(
        dec_b1, dec_b2, dec_w3, dec_b3, src, dst, out);
}

// round 4
// speedup vs baseline: 2.6728x; 1.3091x over previous
#include <cuda_runtime.h>
#include <cuda_bf16.h>
#include <cstdint>
#include <cstddef>
#include <math.h>

// Problem constants (fixed dataset)
#define B_   2
#define E_   160000
#define N_   10000
#define FIN_ 24
#define D_   128
#define P2E_ (2 * E_)

// ---------------- scratch (static __device__, no allocations) ----------------
__device__ float g_emb[(size_t)B_ * E_ * D_];     // edge embeddings [B][E][128]
__device__ float g_edot[2][(size_t)B_ * E_];      // per-layer e_pair . watt[128:256]
__device__ float g_nodeA[(size_t)B_ * N_ * D_];   // node emb after layer 1
__device__ float g_nodeB[(size_t)B_ * N_ * D_];   // node emb after layer 2
__device__ int   g_cnt[N_];
__device__ int   g_cur[N_];
__device__ int   g_off[N_ + 1];
__device__ int   g_adj[P2E_];
// bf16 hi/lo split weights, pre-packed in m16n8k16 B-fragment order
__device__ __align__(16) __nv_bfloat16 g_w1ph[384 * 256];
__device__ __align__(16) __nv_bfloat16 g_w1pl[384 * 256];
__device__ __align__(16) __nv_bfloat16 g_w2ph[256 * 128];
__device__ __align__(16) __nv_bfloat16 g_w2pl[256 * 128];
__device__ __align__(16) __nv_bfloat16 g_ew2ph[128 * 128];
__device__ __align__(16) __nv_bfloat16 g_ew2pl[128 * 128];

// ---------------- helpers ----------------
__device__ __forceinline__ float gelu_f(float x) {
    return 0.5f * x * (1.0f + erff(x * 0.70710678118654752f));
}
__device__ __forceinline__ float wsum(float v) {
#pragma unroll
    for (int o = 16; o; o >>= 1) v += __shfl_xor_sync(0xffffffffu, v, o);
    return v;
}
__device__ __forceinline__ float wmax(float v) {
#pragma unroll
    for (int o = 16; o; o >>= 1) v = fmaxf(v, __shfl_xor_sync(0xffffffffu, v, o));
    return v;
}
__device__ __forceinline__ uint32_t s2u(const void* p) {
    return (uint32_t)__cvta_generic_to_shared(p);
}
__device__ __forceinline__ void cpa16(uint32_t dst, const void* src) {
    asm volatile("cp.async.cg.shared.global [%0], [%1], 16;" :: "r"(dst), "l"(src));
}
__device__ __forceinline__ void cpa_commit() {
    asm volatile("cp.async.commit_group;" ::: "memory");
}
__device__ __forceinline__ void cpa_wait0() {
    asm volatile("cp.async.wait_group 0;" ::: "memory");
}
#define LDMX4(r, addr) \
    asm volatile("ldmatrix.sync.aligned.m8n8.x4.shared.b16 {%0,%1,%2,%3}, [%4];" \
        : "=r"((r)[0]), "=r"((r)[1]), "=r"((r)[2]), "=r"((r)[3]) : "r"(addr))

__device__ __forceinline__ void mma_bf16(float* c, const uint32_t* a,
                                         uint32_t b0, uint32_t b1) {
    asm volatile(
        "mma.sync.aligned.m16n8k16.row.col.f32.bf16.bf16.f32 "
        "{%0,%1,%2,%3},{%4,%5,%6,%7},{%8,%9},{%0,%1,%2,%3};"
        : "+f"(c[0]), "+f"(c[1]), "+f"(c[2]), "+f"(c[3])
        : "r"(a[0]), "r"(a[1]), "r"(a[2]), "r"(a[3]), "r"(b0), "r"(b1));
}

// ---------------- weight pack prep (bf16 hi/lo, B-fragment order) ----------------
// Packed layout: for k16 slice s, col n, tig t, elem j in {2t,2t+1,2t+8,2t+9}:
//   dst[((s*NC + n)*4 + t)*4 + j]
__global__ void pack_weights_kernel(const float* __restrict__ w1,
                                    const float* __restrict__ w2,
                                    const float* __restrict__ ew2) {
    int i = blockIdx.x * blockDim.x + threadIdx.x;
    if (i < 384 * 256) {
        int j = i & 3, t = (i >> 2) & 3, n = (i >> 4) & 255, s = i >> 12;
        int k = s * 16 + 2 * t + (j & 1) + ((j >> 1) << 3);
        float x = w1[k * 256 + n];
        __nv_bfloat16 h = __float2bfloat16_rn(x);
        g_w1ph[i] = h;
        g_w1pl[i] = __float2bfloat16_rn(x - __bfloat162float(h));
    }
    int i2 = i - 384 * 256;
    if (i2 >= 0 && i2 < 256 * 128) {
        int j = i2 & 3, t = (i2 >> 2) & 3, n = (i2 >> 4) & 127, s = i2 >> 11;
        int k = s * 16 + 2 * t + (j & 1) + ((j >> 1) << 3);
        float x = w2[k * 128 + n];
        __nv_bfloat16 h = __float2bfloat16_rn(x);
        g_w2ph[i2] = h;
        g_w2pl[i2] = __float2bfloat16_rn(x - __bfloat162float(h));
    }
    int i3 = i - 384 * 256 - 256 * 128;
    if (i3 >= 0 && i3 < 128 * 128) {
        int j = i3 & 3, t = (i3 >> 2) & 3, n = (i3 >> 4) & 127, s = i3 >> 11;
        int k = s * 16 + 2 * t + (j & 1) + ((j >> 1) << 3);
        float x = ew2[k * 128 + n];
        __nv_bfloat16 h = __float2bfloat16_rn(x);
        g_ew2ph[i3] = h;
        g_ew2pl[i3] = __float2bfloat16_rn(x - __bfloat162float(h));
    }
}

// ---------------- CSR build ----------------
__global__ void zero_cnt_kernel() {
    int i = blockIdx.x * blockDim.x + threadIdx.x;
    if (i < N_) g_cnt[i] = 0;
}

__global__ void count_kernel(const int* __restrict__ src, const int* __restrict__ dst) {
    int idx = blockIdx.x * blockDim.x + threadIdx.x;
    if (idx >= P2E_) return;
    int node = (idx < E_) ? src[idx] : dst[idx - E_];
    atomicAdd(&g_cnt[node], 1);
}

__global__ void scan_kernel() {
    __shared__ int ss[1024];
    int t = threadIdx.x;
    int base = t * 10;                  // 1024*10 >= N_
    int s = 0;
#pragma unroll
    for (int i = 0; i < 10; i++) {
        int idx = base + i;
        if (idx < N_) s += g_cnt[idx];
    }
    ss[t] = s;
    __syncthreads();
    for (int off = 1; off < 1024; off <<= 1) {
        int v = (t >= off) ? ss[t - off] : 0;
        __syncthreads();
        ss[t] += v;
        __syncthreads();
    }
    int run = (t > 0) ? ss[t - 1] : 0;
#pragma unroll
    for (int i = 0; i < 10; i++) {
        int idx = base + i;
        if (idx < N_) {
            g_off[idx] = run;
            run += g_cnt[idx];
            g_cur[idx] = 0;
        }
    }
    if (t == 1023) g_off[N_] = ss[1023];
}

__global__ void fill_kernel(const int* __restrict__ src, const int* __restrict__ dst) {
    int idx = blockIdx.x * blockDim.x + threadIdx.x;
    if (idx >= P2E_) return;
    int node = (idx < E_) ? src[idx] : dst[idx - E_];
    int e    = (idx < E_) ? idx : idx - E_;
    int pos = g_off[node] + atomicAdd(&g_cur[node], 1);
    g_adj[pos] = e;
}

// ---------------- fused edge encoder (GEMM1 scalar, GEMM2 tensorized) ----------------
// 32 rows / 256 thr. smem bytes:
//  eW1s @0 12288 | xs @12288 3072 | eW2H @15360 32768 | eW2L @48128 32768
//  aHi @80896 8704 | aLo @89600 8704
//  vb1 @98304 vg1 @98816 vbe1 @99328 vb2 @99840 vg2 @100352 vbe2 @100864
//  we1 @101376 we2 @101888 (512 each)
//  red @102400 2048 ([32][4][4] f32) | mub @104448 128 | rsb @104576 128
#define ENC_SMEM_BYTES 104704
__global__ void __launch_bounds__(256, 2) encoder_kernel(
    const float* __restrict__ xin,
    const float* __restrict__ w1, const float* __restrict__ b1,
    const float* __restrict__ g1, const float* __restrict__ be1,
    const float* __restrict__ b2,
    const float* __restrict__ g2, const float* __restrict__ be2,
    const float* __restrict__ watt1, const float* __restrict__ watt2)
{
    extern __shared__ char smraw[];
    float* W1s  = (float*)(smraw);
    float* xs   = (float*)(smraw + 12288);
    __nv_bfloat16* eW2H = (__nv_bfloat16*)(smraw + 15360);
    __nv_bfloat16* eW2L = (__nv_bfloat16*)(smraw + 48128);
    __nv_bfloat16* aHi  = (__nv_bfloat16*)(smraw + 80896);
    __nv_bfloat16* aLo  = (__nv_bfloat16*)(smraw + 89600);
    float* vb1  = (float*)(smraw + 98304);
    float* vg1  = (float*)(smraw + 98816);
    float* vbe1 = (float*)(smraw + 99328);
    float* vb2  = (float*)(smraw + 99840);
    float* vg2  = (float*)(smraw + 100352);
    float* vbe2 = (float*)(smraw + 100864);
    float* we1  = (float*)(smraw + 101376);
    float* we2  = (float*)(smraw + 101888);
    float* red  = (float*)(smraw + 102400);
    float* mub  = (float*)(smraw + 104448);
    float* rsb  = (float*)(smraw + 104576);

    int tid = threadIdx.x;
    int b = blockIdx.y;
    int e0 = blockIdx.x * 32;

    uint32_t W1u   = s2u(W1s);
    uint32_t xsu   = s2u(xs);
    uint32_t eW2Hu = s2u(eW2H);
    uint32_t eW2Lu = s2u(eW2L);
    uint32_t aHiU  = s2u(aHi);
    uint32_t aLoU  = s2u(aLo);

    // async prologue: W2 packed (hi+lo), W1, x tile
    for (int i = tid; i < 2048; i += 256) cpa16(eW2Hu + i * 16, g_ew2ph + i * 8);
    for (int i = tid; i < 2048; i += 256) cpa16(eW2Lu + i * 16, g_ew2pl + i * 8);
    for (int i = tid; i < 768; i += 256)  cpa16(W1u + i * 16, w1 + i * 4);
    {
        size_t base = ((size_t)b * E_ + e0) * FIN_;
        if (tid < 192) cpa16(xsu + tid * 16, xin + base + tid * 4);
    }
    cpa_commit();
    if (tid < 128) {
        vb1[tid] = b1[tid];  vg1[tid] = g1[tid];  vbe1[tid] = be1[tid];
        vb2[tid] = b2[tid];  vg2[tid] = g2[tid];  vbe2[tid] = be2[tid];
        we1[tid] = watt1[128 + tid];
        we2[tid] = watt2[128 + tid];
    }
    cpa_wait0();
    __syncthreads();

    int warp = tid >> 5, lane = tid & 31;
    int r0 = warp * 4;
    int c0 = lane * 4;

    // GEMM1: h[32][128] = x[32][24] @ W1 (scalar FMA)
    float acc[4][4];
#pragma unroll
    for (int r = 0; r < 4; r++)
#pragma unroll
        for (int j = 0; j < 4; j++) acc[r][j] = 0.f;

#pragma unroll
    for (int k = 0; k < FIN_; k++) {
        float4 wv = *(float4*)&W1s[k * D_ + c0];
#pragma unroll
        for (int r = 0; r < 4; r++) {
            float a = xs[(r0 + r) * FIN_ + k];
            acc[r][0] = fmaf(a, wv.x, acc[r][0]);
            acc[r][1] = fmaf(a, wv.y, acc[r][1]);
            acc[r][2] = fmaf(a, wv.z, acc[r][2]);
            acc[r][3] = fmaf(a, wv.w, acc[r][3]);
        }
    }
    // +b1, LN1, gelu -> aHi/aLo (bf16 split, stride 136)
#pragma unroll
    for (int r = 0; r < 4; r++) {
        float v[4];
#pragma unroll
        for (int j = 0; j < 4; j++) v[j] = acc[r][j] + vb1[c0 + j];
        float s = wsum(v[0] + v[1] + v[2] + v[3]);
        float mu = s * (1.f / 128.f);
        float d[4], q = 0.f;
#pragma unroll
        for (int j = 0; j < 4; j++) { d[j] = v[j] - mu; q += d[j] * d[j]; }
        q = wsum(q);
        float rstd = rsqrtf(q * (1.f / 128.f) + 1e-5f);
        float g[4];
#pragma unroll
        for (int j = 0; j < 4; j++)
            g[j] = gelu_f(d[j] * rstd * vg1[c0 + j] + vbe1[c0 + j]);
        __nv_bfloat162 h01 = __floats2bfloat162_rn(g[0], g[1]);
        __nv_bfloat162 h23 = __floats2bfloat162_rn(g[2], g[3]);
        __nv_bfloat162 l01 = __floats2bfloat162_rn(
            g[0] - __bfloat162float(h01.x), g[1] - __bfloat162float(h01.y));
        __nv_bfloat162 l23 = __floats2bfloat162_rn(
            g[2] - __bfloat162float(h23.x), g[3] - __bfloat162float(h23.y));
        int o = (r0 + r) * 136 + c0;
        *(__nv_bfloat162*)&aHi[o]     = h01;
        *(__nv_bfloat162*)&aHi[o + 2] = h23;
        *(__nv_bfloat162*)&aLo[o]     = l01;
        *(__nv_bfloat162*)&aLo[o + 2] = l23;
    }
    __syncthreads();

    // GEMM2 (tensor): [32][128] = a[32][128] @ W2. warp tile m16 x n32
    int gid = lane >> 2, tig = lane & 3;
    int arow = lane & 15;
    uint32_t ahalf = (lane >> 4) * 16;
    int m0  = (warp & 1) * 16;
    int wn  = warp >> 1;
    int n0w = wn * 32;

    float acc2[4][4];
#pragma unroll
    for (int nf = 0; nf < 4; nf++)
#pragma unroll
        for (int j = 0; j < 4; j++) acc2[nf][j] = 0.f;

#pragma unroll
    for (int s = 0; s < 8; s++) {
        uint32_t ra = (m0 + arow) * 272 + s * 32 + ahalf;
        uint32_t ah[4], al[4];
        LDMX4(ah, aHiU + ra);
        LDMX4(al, aLoU + ra);
#pragma unroll
        for (int nf = 0; nf < 4; nf++) {
            int n = n0w + nf * 8 + gid;
            int bo = ((s * 128 + n) * 4 + tig) * 4;
            uint2 bh = *(const uint2*)(eW2H + bo);
            uint2 bl = *(const uint2*)(eW2L + bo);
            mma_bf16(acc2[nf], ah, bh.x, bh.y);
            mma_bf16(acc2[nf], al, bh.x, bh.y);
            mma_bf16(acc2[nf], ah, bl.x, bl.y);
        }
    }

    // epilogue: +b2, LN2 (cross-warp), write emb + e_dots
    int rA = m0 + gid, rB = rA + 8;
    {
        float s1 = 0.f, q1 = 0.f, s2 = 0.f, q2 = 0.f;
#pragma unroll
        for (int nf = 0; nf < 4; nf++) {
            int n = n0w + nf * 8 + 2 * tig;
            float vA0 = acc2[nf][0] + vb2[n];
            float vA1 = acc2[nf][1] + vb2[n + 1];
            float vB0 = acc2[nf][2] + vb2[n];
            float vB1 = acc2[nf][3] + vb2[n + 1];
            s1 += vA0 + vA1;  q1 += vA0 * vA0 + vA1 * vA1;
            s2 += vB0 + vB1;  q2 += vB0 * vB0 + vB1 * vB1;
        }
        s1 += __shfl_xor_sync(0xffffffffu, s1, 1);
        s1 += __shfl_xor_sync(0xffffffffu, s1, 2);
        q1 += __shfl_xor_sync(0xffffffffu, q1, 1);
        q1 += __shfl_xor_sync(0xffffffffu, q1, 2);
        s2 += __shfl_xor_sync(0xffffffffu, s2, 1);
        s2 += __shfl_xor_sync(0xffffffffu, s2, 2);
        q2 += __shfl_xor_sync(0xffffffffu, q2, 1);
        q2 += __shfl_xor_sync(0xffffffffu, q2, 2);
        if (tig == 0) {
            red[(rA * 4 + wn) * 4 + 0] = s1;
            red[(rA * 4 + wn) * 4 + 1] = q1;
            red[(rB * 4 + wn) * 4 + 0] = s2;
            red[(rB * 4 + wn) * 4 + 1] = q2;
        }
    }
    __syncthreads();
    if (tid < 32) {
        float S = 0.f, Q = 0.f;
#pragma unroll
        for (int w = 0; w < 4; w++) {
            S += red[(tid * 4 + w) * 4 + 0];
            Q += red[(tid * 4 + w) * 4 + 1];
        }
        float mu = S * (1.f / 128.f);
        float var = Q * (1.f / 128.f) - mu * mu;
        mub[tid] = mu;
        rsb[tid] = rsqrtf(var + 1e-5f);
    }
    __syncthreads();
    {
        float muA = mub[rA], rsA = rsb[rA];
        float muB = mub[rB], rsB = rsb[rB];
        size_t rowA = (size_t)b * E_ + e0 + rA;
        size_t rowB = (size_t)b * E_ + e0 + rB;
        float p1A = 0.f, p2A = 0.f, p1B = 0.f, p2B = 0.f;
#pragma unroll
        for (int nf = 0; nf < 4; nf++) {
            int n = n0w + nf * 8 + 2 * tig;
            float g0 = vg2[n], g1c = vg2[n + 1], e0c = vbe2[n], e1c = vbe2[n + 1];
            float yA0 = (acc2[nf][0] + vb2[n]     - muA) * rsA * g0  + e0c;
            float yA1 = (acc2[nf][1] + vb2[n + 1] - muA) * rsA * g1c + e1c;
            float yB0 = (acc2[nf][2] + vb2[n]     - muB) * rsB * g0  + e0c;
            float yB1 = (acc2[nf][3] + vb2[n + 1] - muB) * rsB * g1c + e1c;
            *(float2*)&g_emb[rowA * D_ + n] = make_float2(yA0, yA1);
            *(float2*)&g_emb[rowB * D_ + n] = make_float2(yB0, yB1);
            p1A += yA0 * we1[n] + yA1 * we1[n + 1];
            p2A += yA0 * we2[n] + yA1 * we2[n + 1];
            p1B += yB0 * we1[n] + yB1 * we1[n + 1];
            p2B += yB0 * we2[n] + yB1 * we2[n + 1];
        }
        p1A += __shfl_xor_sync(0xffffffffu, p1A, 1);
        p1A += __shfl_xor_sync(0xffffffffu, p1A, 2);
        p2A += __shfl_xor_sync(0xffffffffu, p2A, 1);
        p2A += __shfl_xor_sync(0xffffffffu, p2A, 2);
        p1B += __shfl_xor_sync(0xffffffffu, p1B, 1);
        p1B += __shfl_xor_sync(0xffffffffu, p1B, 2);
        p2B += __shfl_xor_sync(0xffffffffu, p2B, 1);
        p2B += __shfl_xor_sync(0xffffffffu, p2B, 2);
        if (tig == 0) {
            red[(rA * 4 + wn) * 4 + 2] = p1A;
            red[(rA * 4 + wn) * 4 + 3] = p2A;
            red[(rB * 4 + wn) * 4 + 2] = p1B;
            red[(rB * 4 + wn) * 4 + 3] = p2B;
        }
    }
    __syncthreads();
    if (tid < 32) {
        float p1 = 0.f, p2 = 0.f;
#pragma unroll
        for (int w = 0; w < 4; w++) {
            p1 += red[(tid * 4 + w) * 4 + 2];
            p2 += red[(tid * 4 + w) * 4 + 3];
        }
        size_t row = (size_t)b * E_ + e0 + tid;
        g_edot[0][row] = p1;
        g_edot[1][row] = p2;
    }
}

// ---------------- message passing (one warp per (batch, node)) ----------------
__global__ void mp_kernel(const float* __restrict__ watt,
                          const float* __restrict__ batt_p, int layer)
{
    int w = (blockIdx.x * blockDim.x + threadIdx.x) >> 5;
    int lane = threadIdx.x & 31;
    if (w >= B_ * N_) return;
    int b = w / N_, n = w % N_;

    const float* node_in = g_nodeA;                 // only read when layer==1
    float* node_out = (layer == 0) ? g_nodeA : g_nodeB;

    float batt = batt_p[0];
    float hd = 0.f;
    float4 cur = make_float4(0.f, 0.f, 0.f, 0.f);
    size_t nrow = ((size_t)b * N_ + n) * D_ + lane * 4;
    if (layer > 0) {
        cur = *(const float4*)&node_in[nrow];
        float4 wh = *(const float4*)&watt[lane * 4];
        float p = cur.x * wh.x + cur.y * wh.y + cur.z * wh.z + cur.w * wh.w;
        hd = wsum(p);
    }

    int start = g_off[n], end = g_off[n + 1];
    int deg = end - start;
    if (deg == 0) {                       // where(deg>0, new, node_b)
        *(float4*)&node_out[nrow] = cur;  // layer0: zeros; layer1: pass-through
        return;
    }

    const float* edot = &g_edot[layer][(size_t)b * E_];

    float m = -1e30f;
    for (int i = start + lane; i < end; i += 32) {
        float s = hd + edot[g_adj[i]] + batt;
        s = (s > 0.f) ? s : 0.2f * s;
        m = fmaxf(m, s);
    }
    m = wmax(m);

    float den = 0.f;
    for (int i = start + lane; i < end; i += 32) {
        float s = hd + edot[g_adj[i]] + batt;
        s = (s > 0.f) ? s : 0.2f * s;
        den += expf(s - m);
    }
    den = wsum(den);

    float4 acc = make_float4(0.f, 0.f, 0.f, 0.f);
    for (int i = start; i < end; i++) {
        int e = g_adj[i];
        float s = hd + edot[e] + batt;
        s = (s > 0.f) ? s : 0.2f * s;
        float p = expf(s - m);
        const float4 v = *(const float4*)&g_emb[((size_t)b * E_ + e) * D_ + lane * 4];
        acc.x = fmaf(p, v.x, acc.x);
        acc.y = fmaf(p, v.y, acc.y);
        acc.z = fmaf(p, v.z, acc.z);
        acc.w = fmaf(p, v.w, acc.w);
    }
    float inv = 1.f / den;
    float4 outv;
    outv.x = gelu_f(acc.x * inv);
    outv.y = gelu_f(acc.y * inv);
    outv.z = gelu_f(acc.z * inv);
    outv.w = gelu_f(acc.w * inv);
    *(float4*)&node_out[nrow] = outv;
}

// ---------------- tensor-core decoder (bf16 split, pipelined staging) ----------------
// 64 rows / 256 thr / 2 CTAs/SM.
// smem bytes:
//   sbH[2] @0,8192 | sbL[2] @16384,24576   (k16 B-slice stages)
//   catHi @32768 5120 | catLo @37888 5120
//   z1Hi @43008 33792 | z1Lo @76800 33792
//   b1s @110592 1024 | b2s @111616 512 | w3s @112128 512 | part @112640 512
//   sn @113152 256 | dn @113408 256  -> 113664
#define DEC_SMEM_BYTES 113664

__global__ void __launch_bounds__(256, 2) decoder_kernel(
    const float* __restrict__ b1, const float* __restrict__ b2,
    const float* __restrict__ w3, const float* __restrict__ b3,
    const int* __restrict__ src, const int* __restrict__ dst,
    float* __restrict__ out)
{
    extern __shared__ char smraw[];
    __nv_bfloat16* catHi = (__nv_bfloat16*)(smraw + 32768);
    __nv_bfloat16* catLo = (__nv_bfloat16*)(smraw + 37888);
    __nv_bfloat16* z1Hi  = (__nv_bfloat16*)(smraw + 43008);
    __nv_bfloat16* z1Lo  = (__nv_bfloat16*)(smraw + 76800);
    float* b1s  = (float*)(smraw + 110592);
    float* b2s  = (float*)(smraw + 111616);
    float* w3s  = (float*)(smraw + 112128);
    float* part = (float*)(smraw + 112640);
    int*   sn   = (int*)(smraw + 113152);
    int*   dn   = (int*)(smraw + 113408);

    int tid  = threadIdx.x;
    int lane = tid & 31;
    int warp = tid >> 5;
    int gid  = lane >> 2;
    int tig  = lane & 3;
    int b    = blockIdx.y;
    int e0   = blockIdx.x * 64;

    if (tid < 64) { sn[tid] = src[e0 + tid]; dn[tid] = dst[e0 + tid]; }
    b1s[tid] = b1[tid];
    if (tid < 128) { b2s[tid] = b2[tid]; w3s[tid] = w3[tid]; }

    const float* nodeb = g_nodeB + (size_t)b * N_ * D_;
    const float* embb  = g_emb   + (size_t)b * E_ * D_;

    uint32_t sbase  = s2u(smraw);
    uint32_t catHiU = s2u(catHi);
    uint32_t catLoU = s2u(catLo);
    uint32_t z1HiU  = s2u(z1Hi);
    uint32_t z1LoU  = s2u(z1Lo);

    int arow  = lane & 15;
    uint32_t ahalf = (lane >> 4) * 16;

    // ---------- GEMM1: warp tile 32x64 ----------
    int m0 = (warp & 1) * 32;
    int n0 = (warp >> 1) * 64;

    float acc[2][8][4];
#pragma unroll
    for (int mf = 0; mf < 2; mf++)
#pragma unroll
        for (int nf = 0; nf < 8; nf++)
#pragma unroll
            for (int j = 0; j < 4; j++) acc[mf][nf][j] = 0.f;

    // prologue: stage B slice 0
    {
        const __nv_bfloat16* pH = g_w1ph;
        const __nv_bfloat16* pL = g_w1pl;
#pragma unroll
        for (int i = tid; i < 512; i += 256) {
            cpa16(sbase + i * 16, pH + i * 8);
            cpa16(sbase + 16384 + i * 16, pL + i * 8);
        }
        cpa_commit();
    }

    for (int s = 0; s < 24; s++) {
        cpa_wait0();
        __syncthreads();   // stage s visible; compute(s-1) done everywhere
        if ((s & 1) == 0) {
            int kc = (s >> 1) * 32;
            // gather cat chunk (cat buffer last read at compute(s-1))
            for (int i = tid; i < 512; i += 256) {
                int r = i >> 3, q = (i & 7) * 4;
                float4 v;
                if (kc < 128)      v = *(const float4*)&nodeb[(size_t)sn[r] * D_ + kc + q];
                else if (kc < 256) v = *(const float4*)&nodeb[(size_t)dn[r] * D_ + kc - 128 + q];
                else               v = *(const float4*)&embb[(size_t)(e0 + r) * D_ + kc - 256 + q];
                __nv_bfloat162 h01 = __floats2bfloat162_rn(v.x, v.y);
                __nv_bfloat162 h23 = __floats2bfloat162_rn(v.z, v.w);
                __nv_bfloat162 l01 = __floats2bfloat162_rn(
                    v.x - __bfloat162float(h01.x), v.y - __bfloat162float(h01.y));
                __nv_bfloat162 l23 = __floats2bfloat162_rn(
                    v.z - __bfloat162float(h23.x), v.w - __bfloat162float(h23.y));
                int o = r * 40 + q;
                *(__nv_bfloat162*)&catHi[o]     = h01;
                *(__nv_bfloat162*)&catHi[o + 2] = h23;
                *(__nv_bfloat162*)&catLo[o]     = l01;
                *(__nv_bfloat162*)&catLo[o + 2] = l23;
            }
        }
        if (s + 1 < 24) {   // stage s+1 into buf (s+1)&1 (its last reader ran before the barrier)
            const __nv_bfloat16* pH = g_w1ph + (s + 1) * 4096;
            const __nv_bfloat16* pL = g_w1pl + (s + 1) * 4096;
            uint32_t dH = sbase + ((s + 1) & 1) * 8192;
            uint32_t dL = sbase + 16384 + ((s + 1) & 1) * 8192;
#pragma unroll
            for (int i = tid; i < 512; i += 256) {
                cpa16(dH + i * 16, pH + i * 8);
                cpa16(dL + i * 16, pL + i * 8);
            }
            cpa_commit();
        }
        if ((s & 1) == 0) __syncthreads();   // cat stores visible
        // compute slice s
        const __nv_bfloat16* stH = (const __nv_bfloat16*)(smraw + (s & 1) * 8192);
        const __nv_bfloat16* stL = (const __nv_bfloat16*)(smraw + 16384 + (s & 1) * 8192);
        uint32_t ab = (s & 1) * 32 + ahalf;
        uint32_t ah[2][4], al[2][4];
#pragma unroll
        for (int mf = 0; mf < 2; mf++) {
            uint32_t ra = (m0 + mf * 16 + arow) * 80 + ab;
            LDMX4(ah[mf], catHiU + ra);
            LDMX4(al[mf], catLoU + ra);
        }
#pragma unroll
        for (int nf = 0; nf < 8; nf++) {
            int n = n0 + nf * 8 + gid;
            int bo = n * 16 + tig * 4;
            uint2 bh = *(const uint2*)(stH + bo);
            uint2 bl = *(const uint2*)(stL + bo);
#pragma unroll
            for (int mf = 0; mf < 2; mf++) {
                mma_bf16(acc[mf][nf], ah[mf], bh.x, bh.y);
                mma_bf16(acc[mf][nf], al[mf], bh.x, bh.y);
                mma_bf16(acc[mf][nf], ah[mf], bl.x, bl.y);
            }
        }
    }

    // GEMM1 epilogue: bias + gelu -> z1 (bf16 hi/lo, own-warp tile)
#pragma unroll
    for (int mf = 0; mf < 2; mf++) {
        int rlo = m0 + mf * 16 + gid;
#pragma unroll
        for (int nf = 0; nf < 8; nf++) {
            int c = n0 + nf * 8 + 2 * tig;
            float v0 = gelu_f(acc[mf][nf][0] + b1s[c]);
            float v1 = gelu_f(acc[mf][nf][1] + b1s[c + 1]);
            float v2 = gelu_f(acc[mf][nf][2] + b1s[c]);
            float v3 = gelu_f(acc[mf][nf][3] + b1s[c + 1]);
            __nv_bfloat162 h01 = __floats2bfloat162_rn(v0, v1);
            __nv_bfloat162 h23 = __floats2bfloat162_rn(v2, v3);
            __nv_bfloat162 l01 = __floats2bfloat162_rn(
                v0 - __bfloat162float(h01.x), v1 - __bfloat162float(h01.y));
            __nv_bfloat162 l23 = __floats2bfloat162_rn(
                v2 - __bfloat162float(h23.x), v3 - __bfloat162float(h23.y));
            *(__nv_bfloat162*)&z1Hi[rlo * 264 + c]       = h01;
            *(__nv_bfloat162*)&z1Hi[(rlo + 8) * 264 + c] = h23;
            *(__nv_bfloat162*)&z1Lo[rlo * 264 + c]       = l01;
            *(__nv_bfloat162*)&z1Lo[(rlo + 8) * 264 + c] = l23;
        }
    }

    // ---------- GEMM2: warp tile 16x64 ----------
    int m20 = (warp & 3) * 16;
    int n20 = (warp >> 2) * 64;

    float acc2[8][4];
#pragma unroll
    for (int nf = 0; nf < 8; nf++)
#pragma unroll
        for (int j = 0; j < 4; j++) acc2[nf][j] = 0.f;

    // prologue: stage B2 slice 0 into buf 0 (last read: G1 slice 22, pre-barrier)
    {
#pragma unroll
        for (int i = tid; i < 256; i += 256) {
            cpa16(sbase + i * 16, g_w2ph + i * 8);
            cpa16(sbase + 16384 + i * 16, g_w2pl + i * 8);
        }
        cpa_commit();
    }

    for (int s = 0; s < 16; s++) {
        cpa_wait0();
        __syncthreads();   // stage s + z1 writes visible
        if (s + 1 < 16) {
            const __nv_bfloat16* pH = g_w2ph + (s + 1) * 2048;
            const __nv_bfloat16* pL = g_w2pl + (s + 1) * 2048;
            uint32_t dH = sbase + ((s + 1) & 1) * 8192;
            uint32_t dL = sbase + 16384 + ((s + 1) & 1) * 8192;
#pragma unroll
            for (int i = tid; i < 256; i += 256) {
                cpa16(dH + i * 16, pH + i * 8);
                cpa16(dL + i * 16, pL + i * 8);
            }
            cpa_commit();
        }
        const __nv_bfloat16* stH = (const __nv_bfloat16*)(smraw + (s & 1) * 8192);
        const __nv_bfloat16* stL = (const __nv_bfloat16*)(smraw + 16384 + (s & 1) * 8192);
        uint32_t ra = (m20 + arow) * 528 + s * 32 + ahalf;
        uint32_t ah[4], al[4];
        LDMX4(ah, z1HiU + ra);
        LDMX4(al, z1LoU + ra);
#pragma unroll
        for (int nf = 0; nf < 8; nf++) {
            int n = n20 + nf * 8 + gid;
            int bo = n * 16 + tig * 4;
            uint2 bh = *(const uint2*)(stH + bo);
            uint2 bl = *(const uint2*)(stL + bo);
            mma_bf16(acc2[nf], ah, bh.x, bh.y);
            mma_bf16(acc2[nf], al, bh.x, bh.y);
            mma_bf16(acc2[nf], ah, bl.x, bl.y);
        }
    }

    // epilogue: gelu(z2 + b2) . w3, reduce over n
    float plo = 0.f, phi = 0.f;
#pragma unroll
    for (int nf = 0; nf < 8; nf++) {
        int c = n20 + nf * 8 + 2 * tig;
        float u0 = gelu_f(acc2[nf][0] + b2s[c]) * w3s[c];
        float u1 = gelu_f(acc2[nf][1] + b2s[c + 1]) * w3s[c + 1];
        float u2 = gelu_f(acc2[nf][2] + b2s[c]) * w3s[c];
        float u3 = gelu_f(acc2[nf][3] + b2s[c + 1]) * w3s[c + 1];
        plo += u0 + u1;
        phi += u2 + u3;
    }
    plo += __shfl_xor_sync(0xffffffffu, plo, 1);
    plo += __shfl_xor_sync(0xffffffffu, plo, 2);
    phi += __shfl_xor_sync(0xffffffffu, phi, 1);
    phi += __shfl_xor_sync(0xffffffffu, phi, 2);
    __syncthreads();
    if (tig == 0) {
        part[(warp >> 2) * 64 + m20 + gid]     = plo;
        part[(warp >> 2) * 64 + m20 + gid + 8] = phi;
    }
    __syncthreads();
    if (tid < 64) {
        out[(size_t)b * E_ + e0 + tid] = part[tid] + part[64 + tid] + b3[0];
    }
}

// ---------------- launch ----------------
extern "C" void kernel_launch(void* const* d_in, const int* in_sizes, int n_in,
                              void* d_out, int out_size)
{
    const float* edge_features = (const float*)d_in[0];
    const float* enc_w1  = (const float*)d_in[1];
    const float* enc_b1  = (const float*)d_in[2];
    const float* enc_g1  = (const float*)d_in[3];
    const float* enc_be1 = (const float*)d_in[4];
    const float* enc_w2  = (const float*)d_in[5];
    const float* enc_b2  = (const float*)d_in[6];
    const float* enc_g2  = (const float*)d_in[7];
    const float* enc_be2 = (const float*)d_in[8];
    const float* watt1   = (const float*)d_in[9];
    const float* batt1   = (const float*)d_in[10];
    const float* watt2   = (const float*)d_in[11];
    const float* batt2   = (const float*)d_in[12];
    const float* dec_w1  = (const float*)d_in[13];
    const float* dec_b1  = (const float*)d_in[14];
    const float* dec_w2  = (const float*)d_in[15];
    const float* dec_b2  = (const float*)d_in[16];
    const float* dec_w3  = (const float*)d_in[17];
    const float* dec_b3  = (const float*)d_in[18];
    const int*   src     = (const int*)d_in[19];
    const int*   dst     = (const int*)d_in[20];
    float* out = (float*)d_out;

    cudaFuncSetAttribute(encoder_kernel, cudaFuncAttributeMaxDynamicSharedMemorySize,
                         ENC_SMEM_BYTES);
    cudaFuncSetAttribute(decoder_kernel, cudaFuncAttributeMaxDynamicSharedMemorySize,
                         DEC_SMEM_BYTES);

    // bf16 fragment-packed weight prep (dec W1, dec W2, enc W2)
    pack_weights_kernel<<<576, 256>>>(dec_w1, dec_w2, enc_w2);

    // CSR part 1
    zero_cnt_kernel<<<(N_ + 255) / 256, 256>>>();
    count_kernel<<<(P2E_ + 255) / 256, 256>>>(src, dst);

    // fused encoder (4th launch -> gets the ncu profile)
    encoder_kernel<<<dim3(E_ / 32, B_), 256, ENC_SMEM_BYTES>>>(
        edge_features, enc_w1, enc_b1, enc_g1, enc_be1,
        enc_b2, enc_g2, enc_be2, watt1, watt2);

    // CSR part 2
    scan_kernel<<<1, 1024>>>();
    fill_kernel<<<(P2E_ + 255) / 256, 256>>>(src, dst);

    // message passing: layer 1 (node_in = 0), layer 2
    int mp_blocks = (B_ * N_ + 7) / 8;   // 8 warps/block
    mp_kernel<<<mp_blocks, 256>>>(watt1, batt1, 0);
    mp_kernel<<<mp_blocks, 256>>>(watt2, batt2, 1);

    // tensor-core decoder MLP (bf16 split, pipelined)
    decoder_kernel<<<dim3(E_ / 64, B_), 256, DEC_SMEM_BYTES>>>(
        dec_b1, dec_b2, dec_w3, dec_b3, src, dst, out);
}

// round 6
// speedup vs baseline: 2.7518x; 1.0296x over previous
#include <cuda_runtime.h>
#include <cuda_bf16.h>
#include <cstdint>
#include <cstddef>
#include <math.h>

// Problem constants (fixed dataset)
#define B_   2
#define E_   160000
#define N_   10000
#define FIN_ 24
#define D_   128
#define P2E_ (2 * E_)
#define NTILE_ (E_ / 32)   // 5000

// ---------------- scratch (static __device__, no allocations) ----------------
__device__ float g_emb[(size_t)B_ * E_ * D_];     // edge embeddings [B][E][128] fp32
__device__ __nv_bfloat16 g_embh[(size_t)B_ * E_ * D_]; // bf16 mirror for MP gather
__device__ float g_edot[2][(size_t)B_ * E_];      // per-layer e_pair . watt[128:256]
__device__ float g_nodeA[(size_t)B_ * N_ * D_];   // node emb after layer 1
__device__ float g_nodeB[(size_t)B_ * N_ * D_];   // node emb after layer 2
__device__ int   g_cnt[N_];
__device__ int   g_cur[N_];
__device__ int   g_off[N_ + 1];
__device__ int   g_adj[P2E_];
// bf16 hi/lo split weights, pre-packed in m16n8k16 B-fragment order
__device__ __align__(16) __nv_bfloat16 g_w1ph[384 * 256];
__device__ __align__(16) __nv_bfloat16 g_w1pl[384 * 256];
__device__ __align__(16) __nv_bfloat16 g_w2ph[256 * 128];
__device__ __align__(16) __nv_bfloat16 g_w2pl[256 * 128];
__device__ __align__(16) __nv_bfloat16 g_ew2ph[128 * 128];
__device__ __align__(16) __nv_bfloat16 g_ew2pl[128 * 128];

// ---------------- helpers ----------------
__device__ __forceinline__ float gelu_f(float x) {
    return 0.5f * x * (1.0f + erff(x * 0.70710678118654752f));
}
__device__ __forceinline__ float wsum(float v) {
#pragma unroll
    for (int o = 16; o; o >>= 1) v += __shfl_xor_sync(0xffffffffu, v, o);
    return v;
}
__device__ __forceinline__ float wmax(float v) {
#pragma unroll
    for (int o = 16; o; o >>= 1) v = fmaxf(v, __shfl_xor_sync(0xffffffffu, v, o));
    return v;
}
__device__ __forceinline__ uint32_t s2u(const void* p) {
    return (uint32_t)__cvta_generic_to_shared(p);
}
__device__ __forceinline__ void cpa16(uint32_t dst, const void* src) {
    asm volatile("cp.async.cg.shared.global [%0], [%1], 16;" :: "r"(dst), "l"(src));
}
__device__ __forceinline__ void cpa_commit() {
    asm volatile("cp.async.commit_group;" ::: "memory");
}
__device__ __forceinline__ void cpa_wait0() {
    asm volatile("cp.async.wait_group 0;" ::: "memory");
}
#define LDMX4(r, addr) \
    asm volatile("ldmatrix.sync.aligned.m8n8.x4.shared.b16 {%0,%1,%2,%3}, [%4];" \
        : "=r"((r)[0]), "=r"((r)[1]), "=r"((r)[2]), "=r"((r)[3]) : "r"(addr))

__device__ __forceinline__ void mma_bf16(float* c, const uint32_t* a,
                                         uint32_t b0, uint32_t b1) {
    asm volatile(
        "mma.sync.aligned.m16n8k16.row.col.f32.bf16.bf16.f32 "
        "{%0,%1,%2,%3},{%4,%5,%6,%7},{%8,%9},{%0,%1,%2,%3};"
        : "+f"(c[0]), "+f"(c[1]), "+f"(c[2]), "+f"(c[3])
        : "r"(a[0]), "r"(a[1]), "r"(a[2]), "r"(a[3]), "r"(b0), "r"(b1));
}

// ---------------- weight pack prep (bf16 hi/lo, B-fragment order) ----------------
__global__ void pack_weights_kernel(const float* __restrict__ w1,
                                    const float* __restrict__ w2,
                                    const float* __restrict__ ew2) {
    int i = blockIdx.x * blockDim.x + threadIdx.x;
    if (i < 384 * 256) {
        int j = i & 3, t = (i >> 2) & 3, n = (i >> 4) & 255, s = i >> 12;
        int k = s * 16 + 2 * t + (j & 1) + ((j >> 1) << 3);
        float x = w1[k * 256 + n];
        __nv_bfloat16 h = __float2bfloat16_rn(x);
        g_w1ph[i] = h;
        g_w1pl[i] = __float2bfloat16_rn(x - __bfloat162float(h));
    }
    int i2 = i - 384 * 256;
    if (i2 >= 0 && i2 < 256 * 128) {
        int j = i2 & 3, t = (i2 >> 2) & 3, n = (i2 >> 4) & 127, s = i2 >> 11;
        int k = s * 16 + 2 * t + (j & 1) + ((j >> 1) << 3);
        float x = w2[k * 128 + n];
        __nv_bfloat16 h = __float2bfloat16_rn(x);
        g_w2ph[i2] = h;
        g_w2pl[i2] = __float2bfloat16_rn(x - __bfloat162float(h));
    }
    int i3 = i - 384 * 256 - 256 * 128;
    if (i3 >= 0 && i3 < 128 * 128) {
        int j = i3 & 3, t = (i3 >> 2) & 3, n = (i3 >> 4) & 127, s = i3 >> 11;
        int k = s * 16 + 2 * t + (j & 1) + ((j >> 1) << 3);
        float x = ew2[k * 128 + n];
        __nv_bfloat16 h = __float2bfloat16_rn(x);
        g_ew2ph[i3] = h;
        g_ew2pl[i3] = __float2bfloat16_rn(x - __bfloat162float(h));
    }
}

// ---------------- CSR build ----------------
__global__ void zero_cnt_kernel() {
    int i = blockIdx.x * blockDim.x + threadIdx.x;
    if (i < N_) g_cnt[i] = 0;
}

__global__ void count_kernel(const int* __restrict__ src, const int* __restrict__ dst) {
    int idx = blockIdx.x * blockDim.x + threadIdx.x;
    if (idx >= P2E_) return;
    int node = (idx < E_) ? src[idx] : dst[idx - E_];
    atomicAdd(&g_cnt[node], 1);
}

__global__ void scan_kernel() {
    __shared__ int ss[1024];
    int t = threadIdx.x;
    int base = t * 10;                  // 1024*10 >= N_
    int s = 0;
#pragma unroll
    for (int i = 0; i < 10; i++) {
        int idx = base + i;
        if (idx < N_) s += g_cnt[idx];
    }
    ss[t] = s;
    __syncthreads();
    for (int off = 1; off < 1024; off <<= 1) {
        int v = (t >= off) ? ss[t - off] : 0;
        __syncthreads();
        ss[t] += v;
        __syncthreads();
    }
    int run = (t > 0) ? ss[t - 1] : 0;
#pragma unroll
    for (int i = 0; i < 10; i++) {
        int idx = base + i;
        if (idx < N_) {
            g_off[idx] = run;
            run += g_cnt[idx];
            g_cur[idx] = 0;
        }
    }
    if (t == 1023) g_off[N_] = ss[1023];
}

__global__ void fill_kernel(const int* __restrict__ src, const int* __restrict__ dst) {
    int idx = blockIdx.x * blockDim.x + threadIdx.x;
    if (idx >= P2E_) return;
    int node = (idx < E_) ? src[idx] : dst[idx - E_];
    int e    = (idx < E_) ? idx : idx - E_;
    int pos = g_off[node] + atomicAdd(&g_cur[node], 1);
    g_adj[pos] = e;
}

// ---------------- persistent fused edge encoder ----------------
// grid (148, B), 256 thr, 2 CTA/SM; each CTA grid-strides over 32-row tiles.
// Weights loaded to smem ONCE per CTA. x tiles double-buffered via cp.async.
#define ENC_SMEM_BYTES 107776
__global__ void __launch_bounds__(256, 2) encoder_kernel(
    const float* __restrict__ xin,
    const float* __restrict__ w1, const float* __restrict__ b1,
    const float* __restrict__ g1, const float* __restrict__ be1,
    const float* __restrict__ b2,
    const float* __restrict__ g2, const float* __restrict__ be2,
    const float* __restrict__ watt1, const float* __restrict__ watt2)
{
    extern __shared__ char smraw[];
    float* W1s  = (float*)(smraw);
    float* xs   = (float*)(smraw + 12288);   // two 768-float buffers
    __nv_bfloat16* eW2H = (__nv_bfloat16*)(smraw + 18432);
    __nv_bfloat16* eW2L = (__nv_bfloat16*)(smraw + 51200);
    __nv_bfloat16* aHi  = (__nv_bfloat16*)(smraw + 83968);
    __nv_bfloat16* aLo  = (__nv_bfloat16*)(smraw + 92672);
    float* vb1  = (float*)(smraw + 101376);
    float* vg1  = (float*)(smraw + 101888);
    float* vbe1 = (float*)(smraw + 102400);
    float* vb2  = (float*)(smraw + 102912);
    float* vg2  = (float*)(smraw + 103424);
    float* vbe2 = (float*)(smraw + 103936);
    float* we1  = (float*)(smraw + 104448);
    float* we2  = (float*)(smraw + 104960);
    float* red  = (float*)(smraw + 105472);
    float* mub  = (float*)(smraw + 107520);
    float* rsb  = (float*)(smraw + 107648);

    int tid = threadIdx.x;
    int b = blockIdx.y;

    uint32_t W1u   = s2u(W1s);
    uint32_t xsu   = s2u(xs);
    uint32_t eW2Hu = s2u(eW2H);
    uint32_t eW2Lu = s2u(eW2L);
    uint32_t aHiU  = s2u(aHi);
    uint32_t aLoU  = s2u(aLo);

    // one-time prologue: W2 packed (hi+lo), W1, first x tile
    for (int i = tid; i < 2048; i += 256) cpa16(eW2Hu + i * 16, g_ew2ph + i * 8);
    for (int i = tid; i < 2048; i += 256) cpa16(eW2Lu + i * 16, g_ew2pl + i * 8);
    for (int i = tid; i < 768; i += 256)  cpa16(W1u + i * 16, w1 + i * 4);
    {
        size_t base = ((size_t)b * E_ + (size_t)blockIdx.x * 32) * FIN_;
        if (tid < 192) cpa16(xsu + tid * 16, xin + base + tid * 4);
    }
    cpa_commit();
    if (tid < 128) {
        vb1[tid] = b1[tid];  vg1[tid] = g1[tid];  vbe1[tid] = be1[tid];
        vb2[tid] = b2[tid];  vg2[tid] = g2[tid];  vbe2[tid] = be2[tid];
        we1[tid] = watt1[128 + tid];
        we2[tid] = watt2[128 + tid];
    }
    cpa_wait0();
    __syncthreads();

    int warp = tid >> 5, lane = tid & 31;
    int r0 = warp * 4;
    int c0 = lane * 4;
    int gid = lane >> 2, tig = lane & 3;
    int arow = lane & 15;
    uint32_t ahalf = (lane >> 4) * 16;
    int m0  = (warp & 1) * 16;
    int wn  = warp >> 1;
    int n0w = wn * 32;

    int p = 0;
    for (int t = blockIdx.x; t < NTILE_; t += gridDim.x) {
        int e0 = t * 32;
        const float* xb = xs + p * 768;

        // GEMM1: h[32][128] = x[32][24] @ W1 (scalar FMA)
        float acc[4][4];
#pragma unroll
        for (int r = 0; r < 4; r++)
#pragma unroll
            for (int j = 0; j < 4; j++) acc[r][j] = 0.f;

#pragma unroll
        for (int k = 0; k < FIN_; k++) {
            float4 wv = *(float4*)&W1s[k * D_ + c0];
#pragma unroll
            for (int r = 0; r < 4; r++) {
                float a = xb[(r0 + r) * FIN_ + k];
                acc[r][0] = fmaf(a, wv.x, acc[r][0]);
                acc[r][1] = fmaf(a, wv.y, acc[r][1]);
                acc[r][2] = fmaf(a, wv.z, acc[r][2]);
                acc[r][3] = fmaf(a, wv.w, acc[r][3]);
            }
        }
        // +b1, LN1, gelu -> aHi/aLo (bf16 split, stride 136)
#pragma unroll
        for (int r = 0; r < 4; r++) {
            float v[4];
#pragma unroll
            for (int j = 0; j < 4; j++) v[j] = acc[r][j] + vb1[c0 + j];
            float s = wsum(v[0] + v[1] + v[2] + v[3]);
            float mu = s * (1.f / 128.f);
            float d[4], q = 0.f;
#pragma unroll
            for (int j = 0; j < 4; j++) { d[j] = v[j] - mu; q += d[j] * d[j]; }
            q = wsum(q);
            float rstd = rsqrtf(q * (1.f / 128.f) + 1e-5f);
            float g[4];
#pragma unroll
            for (int j = 0; j < 4; j++)
                g[j] = gelu_f(d[j] * rstd * vg1[c0 + j] + vbe1[c0 + j]);
            __nv_bfloat162 h01 = __floats2bfloat162_rn(g[0], g[1]);
            __nv_bfloat162 h23 = __floats2bfloat162_rn(g[2], g[3]);
            __nv_bfloat162 l01 = __floats2bfloat162_rn(
                g[0] - __bfloat162float(h01.x), g[1] - __bfloat162float(h01.y));
            __nv_bfloat162 l23 = __floats2bfloat162_rn(
                g[2] - __bfloat162float(h23.x), g[3] - __bfloat162float(h23.y));
            int o = (r0 + r) * 136 + c0;
            *(__nv_bfloat162*)&aHi[o]     = h01;
            *(__nv_bfloat162*)&aHi[o + 2] = h23;
            *(__nv_bfloat162*)&aLo[o]     = l01;
            *(__nv_bfloat162*)&aLo[o + 2] = l23;
        }
        __syncthreads();   // aHi/aLo visible; xs[p] fully consumed

        // prefetch next x tile into buffer p^1
        {
            int tn = t + gridDim.x;
            if (tn < NTILE_) {
                size_t base = ((size_t)b * E_ + (size_t)tn * 32) * FIN_;
                if (tid < 192) cpa16(xsu + (p ^ 1) * 3072 + tid * 16, xin + base + tid * 4);
                cpa_commit();
            }
        }

        // GEMM2 (tensor): [32][128] = a[32][128] @ W2. warp tile m16 x n32
        float acc2[4][4];
#pragma unroll
        for (int nf = 0; nf < 4; nf++)
#pragma unroll
            for (int j = 0; j < 4; j++) acc2[nf][j] = 0.f;

#pragma unroll
        for (int s = 0; s < 8; s++) {
            uint32_t ra = (m0 + arow) * 272 + s * 32 + ahalf;
            uint32_t ah[4], al[4];
            LDMX4(ah, aHiU + ra);
            LDMX4(al, aLoU + ra);
#pragma unroll
            for (int nf = 0; nf < 4; nf++) {
                int n = n0w + nf * 8 + gid;
                int bo = ((s * 128 + n) * 4 + tig) * 4;
                uint2 bh = *(const uint2*)(eW2H + bo);
                uint2 bl = *(const uint2*)(eW2L + bo);
                mma_bf16(acc2[nf], ah, bh.x, bh.y);
                mma_bf16(acc2[nf], al, bh.x, bh.y);
                mma_bf16(acc2[nf], ah, bl.x, bl.y);
            }
        }

        // epilogue: +b2, LN2 (cross-warp), write emb (fp32 + bf16) + e_dots
        int rA = m0 + gid, rB = rA + 8;
        {
            float s1 = 0.f, q1 = 0.f, s2 = 0.f, q2 = 0.f;
#pragma unroll
            for (int nf = 0; nf < 4; nf++) {
                int n = n0w + nf * 8 + 2 * tig;
                float vA0 = acc2[nf][0] + vb2[n];
                float vA1 = acc2[nf][1] + vb2[n + 1];
                float vB0 = acc2[nf][2] + vb2[n];
                float vB1 = acc2[nf][3] + vb2[n + 1];
                s1 += vA0 + vA1;  q1 += vA0 * vA0 + vA1 * vA1;
                s2 += vB0 + vB1;  q2 += vB0 * vB0 + vB1 * vB1;
            }
            s1 += __shfl_xor_sync(0xffffffffu, s1, 1);
            s1 += __shfl_xor_sync(0xffffffffu, s1, 2);
            q1 += __shfl_xor_sync(0xffffffffu, q1, 1);
            q1 += __shfl_xor_sync(0xffffffffu, q1, 2);
            s2 += __shfl_xor_sync(0xffffffffu, s2, 1);
            s2 += __shfl_xor_sync(0xffffffffu, s2, 2);
            q2 += __shfl_xor_sync(0xffffffffu, q2, 1);
            q2 += __shfl_xor_sync(0xffffffffu, q2, 2);
            if (tig == 0) {
                red[(rA * 4 + wn) * 4 + 0] = s1;
                red[(rA * 4 + wn) * 4 + 1] = q1;
                red[(rB * 4 + wn) * 4 + 0] = s2;
                red[(rB * 4 + wn) * 4 + 1] = q2;
            }
        }
        __syncthreads();
        if (tid < 32) {
            float S = 0.f, Q = 0.f;
#pragma unroll
            for (int w = 0; w < 4; w++) {
                S += red[(tid * 4 + w) * 4 + 0];
                Q += red[(tid * 4 + w) * 4 + 1];
            }
            float mu = S * (1.f / 128.f);
            float var = Q * (1.f / 128.f) - mu * mu;
            mub[tid] = mu;
            rsb[tid] = rsqrtf(var + 1e-5f);
        }
        __syncthreads();
        {
            float muA = mub[rA], rsA = rsb[rA];
            float muB = mub[rB], rsB = rsb[rB];
            size_t rowA = (size_t)b * E_ + e0 + rA;
            size_t rowB = (size_t)b * E_ + e0 + rB;
            float p1A = 0.f, p2A = 0.f, p1B = 0.f, p2B = 0.f;
#pragma unroll
            for (int nf = 0; nf < 4; nf++) {
                int n = n0w + nf * 8 + 2 * tig;
                float g0 = vg2[n], g1c = vg2[n + 1], e0c = vbe2[n], e1c = vbe2[n + 1];
                float yA0 = (acc2[nf][0] + vb2[n]     - muA) * rsA * g0  + e0c;
                float yA1 = (acc2[nf][1] + vb2[n + 1] - muA) * rsA * g1c + e1c;
                float yB0 = (acc2[nf][2] + vb2[n]     - muB) * rsB * g0  + e0c;
                float yB1 = (acc2[nf][3] + vb2[n + 1] - muB) * rsB * g1c + e1c;
                *(float2*)&g_emb[rowA * D_ + n] = make_float2(yA0, yA1);
                *(float2*)&g_emb[rowB * D_ + n] = make_float2(yB0, yB1);
                *(__nv_bfloat162*)&g_embh[rowA * D_ + n] = __floats2bfloat162_rn(yA0, yA1);
                *(__nv_bfloat162*)&g_embh[rowB * D_ + n] = __floats2bfloat162_rn(yB0, yB1);
                p1A += yA0 * we1[n] + yA1 * we1[n + 1];
                p2A += yA0 * we2[n] + yA1 * we2[n + 1];
                p1B += yB0 * we1[n] + yB1 * we1[n + 1];
                p2B += yB0 * we2[n] + yB1 * we2[n + 1];
            }
            p1A += __shfl_xor_sync(0xffffffffu, p1A, 1);
            p1A += __shfl_xor_sync(0xffffffffu, p1A, 2);
            p2A += __shfl_xor_sync(0xffffffffu, p2A, 1);
            p2A += __shfl_xor_sync(0xffffffffu, p2A, 2);
            p1B += __shfl_xor_sync(0xffffffffu, p1B, 1);
            p1B += __shfl_xor_sync(0xffffffffu, p1B, 2);
            p2B += __shfl_xor_sync(0xffffffffu, p2B, 1);
            p2B += __shfl_xor_sync(0xffffffffu, p2B, 2);
            if (tig == 0) {
                red[(rA * 4 + wn) * 4 + 2] = p1A;
                red[(rA * 4 + wn) * 4 + 3] = p2A;
                red[(rB * 4 + wn) * 4 + 2] = p1B;
                red[(rB * 4 + wn) * 4 + 3] = p2B;
            }
        }
        __syncthreads();
        if (tid < 32) {
            float p1 = 0.f, p2 = 0.f;
#pragma unroll
            for (int w = 0; w < 4; w++) {
                p1 += red[(tid * 4 + w) * 4 + 2];
                p2 += red[(tid * 4 + w) * 4 + 3];
            }
            size_t row = (size_t)b * E_ + e0 + tid;
            g_edot[0][row] = p1;
            g_edot[1][row] = p2;
        }
        cpa_wait0();       // next x tile landed
        __syncthreads();   // red/aHi free for next tile
        p ^= 1;
    }
}

// ---------------- message passing (one warp per (batch, node)) ----------------
__global__ void mp_kernel(const float* __restrict__ watt,
                          const float* __restrict__ batt_p, int layer)
{
    int w = (blockIdx.x * blockDim.x + threadIdx.x) >> 5;
    int lane = threadIdx.x & 31;
    if (w >= B_ * N_) return;
    int b = w / N_, n = w % N_;

    const float* node_in = g_nodeA;                 // only read when layer==1
    float* node_out = (layer == 0) ? g_nodeA : g_nodeB;

    float batt = batt_p[0];
    float hd = 0.f;
    float4 cur = make_float4(0.f, 0.f, 0.f, 0.f);
    size_t nrow = ((size_t)b * N_ + n) * D_ + lane * 4;
    if (layer > 0) {
        cur = *(const float4*)&node_in[nrow];
        float4 wh = *(const float4*)&watt[lane * 4];
        float p = cur.x * wh.x + cur.y * wh.y + cur.z * wh.z + cur.w * wh.w;
        hd = wsum(p);
    }

    int start = g_off[n], end = g_off[n + 1];
    int deg = end - start;
    if (deg == 0) {                       // where(deg>0, new, node_b)
        *(float4*)&node_out[nrow] = cur;  // layer0: zeros; layer1: pass-through
        return;
    }

    const float* edot = &g_edot[layer][(size_t)b * E_];
    const __nv_bfloat16* embh = g_embh + (size_t)b * E_ * D_;

    float m = -1e30f;
    for (int i = start + lane; i < end; i += 32) {
        float s = hd + edot[g_adj[i]] + batt;
        s = (s > 0.f) ? s : 0.2f * s;
        m = fmaxf(m, s);
    }
    m = wmax(m);

    float den = 0.f;
    for (int i = start + lane; i < end; i += 32) {
        float s = hd + edot[g_adj[i]] + batt;
        s = (s > 0.f) ? s : 0.2f * s;
        den += expf(s - m);
    }
    den = wsum(den);

    float4 acc = make_float4(0.f, 0.f, 0.f, 0.f);
    for (int i = start; i < end; i++) {
        int e = g_adj[i];
        float s = hd + edot[e] + batt;
        s = (s > 0.f) ? s : 0.2f * s;
        float p = expf(s - m);
        uint2 raw = *(const uint2*)&embh[(size_t)e * D_ + lane * 4];
        __nv_bfloat162 v01 = *(__nv_bfloat162*)&raw.x;
        __nv_bfloat162 v23 = *(__nv_bfloat162*)&raw.y;
        float2 f01 = __bfloat1622float2(v01);
        float2 f23 = __bfloat1622float2(v23);
        acc.x = fmaf(p, f01.x, acc.x);
        acc.y = fmaf(p, f01.y, acc.y);
        acc.z = fmaf(p, f23.x, acc.z);
        acc.w = fmaf(p, f23.y, acc.w);
    }
    float inv = 1.f / den;
    float4 outv;
    outv.x = gelu_f(acc.x * inv);
    outv.y = gelu_f(acc.y * inv);
    outv.z = gelu_f(acc.z * inv);
    outv.w = gelu_f(acc.w * inv);
    *(float4*)&node_out[nrow] = outv;
}

// ---------------- tensor-core decoder (bf16 split, pipelined staging) ----------------
#define DEC_SMEM_BYTES 113664

__global__ void __launch_bounds__(256, 2) decoder_kernel(
    const float* __restrict__ b1, const float* __restrict__ b2,
    const float* __restrict__ w3, const float* __restrict__ b3,
    const int* __restrict__ src, const int* __restrict__ dst,
    float* __restrict__ out)
{
    extern __shared__ char smraw[];
    __nv_bfloat16* catHi = (__nv_bfloat16*)(smraw + 32768);
    __nv_bfloat16* catLo = (__nv_bfloat16*)(smraw + 37888);
    __nv_bfloat16* z1Hi  = (__nv_bfloat16*)(smraw + 43008);
    __nv_bfloat16* z1Lo  = (__nv_bfloat16*)(smraw + 76800);
    float* b1s  = (float*)(smraw + 110592);
    float* b2s  = (float*)(smraw + 111616);
    float* w3s  = (float*)(smraw + 112128);
    float* part = (float*)(smraw + 112640);
    int*   sn   = (int*)(smraw + 113152);
    int*   dn   = (int*)(smraw + 113408);

    int tid  = threadIdx.x;
    int lane = tid & 31;
    int warp = tid >> 5;
    int gid  = lane >> 2;
    int tig  = lane & 3;
    int b    = blockIdx.y;
    int e0   = blockIdx.x * 64;

    if (tid < 64) { sn[tid] = src[e0 + tid]; dn[tid] = dst[e0 + tid]; }
    b1s[tid] = b1[tid];
    if (tid < 128) { b2s[tid] = b2[tid]; w3s[tid] = w3[tid]; }

    const float* nodeb = g_nodeB + (size_t)b * N_ * D_;
    const float* embb  = g_emb   + (size_t)b * E_ * D_;

    uint32_t sbase  = s2u(smraw);
    uint32_t catHiU = s2u(catHi);
    uint32_t catLoU = s2u(catLo);
    uint32_t z1HiU  = s2u(z1Hi);
    uint32_t z1LoU  = s2u(z1Lo);

    int arow  = lane & 15;
    uint32_t ahalf = (lane >> 4) * 16;

    // ---------- GEMM1: warp tile 32x64 ----------
    int m0 = (warp & 1) * 32;
    int n0 = (warp >> 1) * 64;

    float acc[2][8][4];
#pragma unroll
    for (int mf = 0; mf < 2; mf++)
#pragma unroll
        for (int nf = 0; nf < 8; nf++)
#pragma unroll
            for (int j = 0; j < 4; j++) acc[mf][nf][j] = 0.f;

    // prologue: stage B slice 0
    {
        const __nv_bfloat16* pH = g_w1ph;
        const __nv_bfloat16* pL = g_w1pl;
#pragma unroll
        for (int i = tid; i < 512; i += 256) {
            cpa16(sbase + i * 16, pH + i * 8);
            cpa16(sbase + 16384 + i * 16, pL + i * 8);
        }
        cpa_commit();
    }

    for (int s = 0; s < 24; s++) {
        cpa_wait0();
        __syncthreads();   // stage s visible; compute(s-1) done everywhere
        if ((s & 1) == 0) {
            int kc = (s >> 1) * 32;
            for (int i = tid; i < 512; i += 256) {
                int r = i >> 3, q = (i & 7) * 4;
                float4 v;
                if (kc < 128)      v = *(const float4*)&nodeb[(size_t)sn[r] * D_ + kc + q];
                else if (kc < 256) v = *(const float4*)&nodeb[(size_t)dn[r] * D_ + kc - 128 + q];
                else               v = *(const float4*)&embb[(size_t)(e0 + r) * D_ + kc - 256 + q];
                __nv_bfloat162 h01 = __floats2bfloat162_rn(v.x, v.y);
                __nv_bfloat162 h23 = __floats2bfloat162_rn(v.z, v.w);
                __nv_bfloat162 l01 = __floats2bfloat162_rn(
                    v.x - __bfloat162float(h01.x), v.y - __bfloat162float(h01.y));
                __nv_bfloat162 l23 = __floats2bfloat162_rn(
                    v.z - __bfloat162float(h23.x), v.w - __bfloat162float(h23.y));
                int o = r * 40 + q;
                *(__nv_bfloat162*)&catHi[o]     = h01;
                *(__nv_bfloat162*)&catHi[o + 2] = h23;
                *(__nv_bfloat162*)&catLo[o]     = l01;
                *(__nv_bfloat162*)&catLo[o + 2] = l23;
            }
        }
        if (s + 1 < 24) {
            const __nv_bfloat16* pH = g_w1ph + (s + 1) * 4096;
            const __nv_bfloat16* pL = g_w1pl + (s + 1) * 4096;
            uint32_t dH = sbase + ((s + 1) & 1) * 8192;
            uint32_t dL = sbase + 16384 + ((s + 1) & 1) * 8192;
#pragma unroll
            for (int i = tid; i < 512; i += 256) {
                cpa16(dH + i * 16, pH + i * 8);
                cpa16(dL + i * 16, pL + i * 8);
            }
            cpa_commit();
        }
        if ((s & 1) == 0) __syncthreads();   // cat stores visible
        const __nv_bfloat16* stH = (const __nv_bfloat16*)(smraw + (s & 1) * 8192);
        const __nv_bfloat16* stL = (const __nv_bfloat16*)(smraw + 16384 + (s & 1) * 8192);
        uint32_t ab = (s & 1) * 32 + ahalf;
        uint32_t ah[2][4], al[2][4];
#pragma unroll
        for (int mf = 0; mf < 2; mf++) {
            uint32_t ra = (m0 + mf * 16 + arow) * 80 + ab;
            LDMX4(ah[mf], catHiU + ra);
            LDMX4(al[mf], catLoU + ra);
        }
#pragma unroll
        for (int nf = 0; nf < 8; nf++) {
            int n = n0 + nf * 8 + gid;
            int bo = n * 16 + tig * 4;
            uint2 bh = *(const uint2*)(stH + bo);
            uint2 bl = *(const uint2*)(stL + bo);
#pragma unroll
            for (int mf = 0; mf < 2; mf++) {
                mma_bf16(acc[mf][nf], ah[mf], bh.x, bh.y);
                mma_bf16(acc[mf][nf], al[mf], bh.x, bh.y);
                mma_bf16(acc[mf][nf], ah[mf], bl.x, bl.y);
            }
        }
    }

    // GEMM1 epilogue: bias + gelu -> z1 (bf16 hi/lo, own-warp tile)
#pragma unroll
    for (int mf = 0; mf < 2; mf++) {
        int rlo = m0 + mf * 16 + gid;
#pragma unroll
        for (int nf = 0; nf < 8; nf++) {
            int c = n0 + nf * 8 + 2 * tig;
            float v0 = gelu_f(acc[mf][nf][0] + b1s[c]);
            float v1 = gelu_f(acc[mf][nf][1] + b1s[c + 1]);
            float v2 = gelu_f(acc[mf][nf][2] + b1s[c]);
            float v3 = gelu_f(acc[mf][nf][3] + b1s[c + 1]);
            __nv_bfloat162 h01 = __floats2bfloat162_rn(v0, v1);
            __nv_bfloat162 h23 = __floats2bfloat162_rn(v2, v3);
            __nv_bfloat162 l01 = __floats2bfloat162_rn(
                v0 - __bfloat162float(h01.x), v1 - __bfloat162float(h01.y));
            __nv_bfloat162 l23 = __floats2bfloat162_rn(
                v2 - __bfloat162float(h23.x), v3 - __bfloat162float(h23.y));
            *(__nv_bfloat162*)&z1Hi[rlo * 264 + c]       = h01;
            *(__nv_bfloat162*)&z1Hi[(rlo + 8) * 264 + c] = h23;
            *(__nv_bfloat162*)&z1Lo[rlo * 264 + c]       = l01;
            *(__nv_bfloat162*)&z1Lo[(rlo + 8) * 264 + c] = l23;
        }
    }

    // ---------- GEMM2: warp tile 16x64 ----------
    int m20 = (warp & 3) * 16;
    int n20 = (warp >> 2) * 64;

    float acc2[8][4];
#pragma unroll
    for (int nf = 0; nf < 8; nf++)
#pragma unroll
        for (int j = 0; j < 4; j++) acc2[nf][j] = 0.f;

    // prologue: stage B2 slice 0 into buf 0
    {
#pragma unroll
        for (int i = tid; i < 256; i += 256) {
            cpa16(sbase + i * 16, g_w2ph + i * 8);
            cpa16(sbase + 16384 + i * 16, g_w2pl + i * 8);
        }
        cpa_commit();
    }

    for (int s = 0; s < 16; s++) {
        cpa_wait0();
        __syncthreads();   // stage s + z1 writes visible
        if (s + 1 < 16) {
            const __nv_bfloat16* pH = g_w2ph + (s + 1) * 2048;
            const __nv_bfloat16* pL = g_w2pl + (s + 1) * 2048;
            uint32_t dH = sbase + ((s + 1) & 1) * 8192;
            uint32_t dL = sbase + 16384 + ((s + 1) & 1) * 8192;
#pragma unroll
            for (int i = tid; i < 256; i += 256) {
                cpa16(dH + i * 16, pH + i * 8);
                cpa16(dL + i * 16, pL + i * 8);
            }
            cpa_commit();
        }
        const __nv_bfloat16* stH = (const __nv_bfloat16*)(smraw + (s & 1) * 8192);
        const __nv_bfloat16* stL = (const __nv_bfloat16*)(smraw + 16384 + (s & 1) * 8192);
        uint32_t ra = (m20 + arow) * 528 + s * 32 + ahalf;
        uint32_t ah[4], al[4];
        LDMX4(ah, z1HiU + ra);
        LDMX4(al, z1LoU + ra);
#pragma unroll
        for (int nf = 0; nf < 8; nf++) {
            int n = n20 + nf * 8 + gid;
            int bo = n * 16 + tig * 4;
            uint2 bh = *(const uint2*)(stH + bo);
            uint2 bl = *(const uint2*)(stL + bo);
            mma_bf16(acc2[nf], ah, bh.x, bh.y);
            mma_bf16(acc2[nf], al, bh.x, bh.y);
            mma_bf16(acc2[nf], ah, bl.x, bl.y);
        }
    }

    // epilogue: gelu(z2 + b2) . w3, reduce over n
    float plo = 0.f, phi = 0.f;
#pragma unroll
    for (int nf = 0; nf < 8; nf++) {
        int c = n20 + nf * 8 + 2 * tig;
        float u0 = gelu_f(acc2[nf][0] + b2s[c]) * w3s[c];
        float u1 = gelu_f(acc2[nf][1] + b2s[c + 1]) * w3s[c + 1];
        float u2 = gelu_f(acc2[nf][2] + b2s[c]) * w3s[c];
        float u3 = gelu_f(acc2[nf][3] + b2s[c + 1]) * w3s[c + 1];
        plo += u0 + u1;
        phi += u2 + u3;
    }
    plo += __shfl_xor_sync(0xffffffffu, plo, 1);
    plo += __shfl_xor_sync(0xffffffffu, plo, 2);
    phi += __shfl_xor_sync(0xffffffffu, phi, 1);
    phi += __shfl_xor_sync(0xffffffffu, phi, 2);
    __syncthreads();
    if (tig == 0) {
        part[(warp >> 2) * 64 + m20 + gid]     = plo;
        part[(warp >> 2) * 64 + m20 + gid + 8] = phi;
    }
    __syncthreads();
    if (tid < 64) {
        out[(size_t)b * E_ + e0 + tid] = part[tid] + part[64 + tid] + b3[0];
    }
}

// ---------------- launch ----------------
extern "C" void kernel_launch(void* const* d_in, const int* in_sizes, int n_in,
                              void* d_out, int out_size)
{
    const float* edge_features = (const float*)d_in[0];
    const float* enc_w1  = (const float*)d_in[1];
    const float* enc_b1  = (const float*)d_in[2];
    const float* enc_g1  = (const float*)d_in[3];
    const float* enc_be1 = (const float*)d_in[4];
    const float* enc_w2  = (const float*)d_in[5];
    const float* enc_b2  = (const float*)d_in[6];
    const float* enc_g2  = (const float*)d_in[7];
    const float* enc_be2 = (const float*)d_in[8];
    const float* watt1   = (const float*)d_in[9];
    const float* batt1   = (const float*)d_in[10];
    const float* watt2   = (const float*)d_in[11];
    const float* batt2   = (const float*)d_in[12];
    const float* dec_w1  = (const float*)d_in[13];
    const float* dec_b1  = (const float*)d_in[14];
    const float* dec_w2  = (const float*)d_in[15];
    const float* dec_b2  = (const float*)d_in[16];
    const float* dec_w3  = (const float*)d_in[17];
    const float* dec_b3  = (const float*)d_in[18];
    const int*   src     = (const int*)d_in[19];
    const int*   dst     = (const int*)d_in[20];
    float* out = (float*)d_out;

    cudaFuncSetAttribute(encoder_kernel, cudaFuncAttributeMaxDynamicSharedMemorySize,
                         ENC_SMEM_BYTES);
    cudaFuncSetAttribute(decoder_kernel, cudaFuncAttributeMaxDynamicSharedMemorySize,
                         DEC_SMEM_BYTES);

    // bf16 fragment-packed weight prep (dec W1, dec W2, enc W2)
    pack_weights_kernel<<<576, 256>>>(dec_w1, dec_w2, enc_w2);

    // CSR part 1
    zero_cnt_kernel<<<(N_ + 255) / 256, 256>>>();
    count_kernel<<<(P2E_ + 255) / 256, 256>>>(src, dst);

    // persistent fused encoder (4th launch -> gets the ncu profile)
    encoder_kernel<<<dim3(148, B_), 256, ENC_SMEM_BYTES>>>(
        edge_features, enc_w1, enc_b1, enc_g1, enc_be1,
        enc_b2, enc_g2, enc_be2, watt1, watt2);

    // CSR part 2
    scan_kernel<<<1, 1024>>>();
    fill_kernel<<<(P2E_ + 255) / 256, 256>>>(src, dst);

    // message passing: layer 1 (node_in = 0), layer 2
    int mp_blocks = (B_ * N_ + 7) / 8;   // 8 warps/block
    mp_kernel<<<mp_blocks, 256>>>(watt1, batt1, 0);
    mp_kernel<<<mp_blocks, 256>>>(watt2, batt2, 1);

    // tensor-core decoder MLP (bf16 split, pipelined)
    decoder_kernel<<<dim3(E_ / 64, B_), 256, DEC_SMEM_BYTES>>>(
        dec_b1, dec_b2, dec_w3, dec_b3, src, dst, out);
}